// round 3
// baseline (speedup 1.0000x reference)
#include <cuda_runtime.h>
#include <math.h>

#define DIMC  1024
#define NHEAD 16
#define HDIM  64
#define BQ    2
#define NSEQ  2048
#define ROWS  (BQ*NSEQ)      // 4096
#define QKV_F (3*DIMC)       // 3072

typedef unsigned long long u64t;

__device__ __forceinline__ u64t pack2(float lo, float hi) {
    u64t r; asm("mov.b64 %0, {%1, %2};" : "=l"(r) : "f"(lo), "f"(hi)); return r;
}
__device__ __forceinline__ void unpack2(u64t v, float& lo, float& hi) {
    asm("mov.b64 {%0, %1}, %2;" : "=f"(lo), "=f"(hi) : "l"(v));
}
__device__ __forceinline__ u64t fma2(u64t a, u64t b, u64t c) {
    u64t d; asm("fma.rn.f32x2 %0, %1, %2, %3;" : "=l"(d) : "l"(a), "l"(b), "l"(c)); return d;
}
__device__ __forceinline__ u64t mul2(u64t a, u64t b) {
    u64t d; asm("mul.rn.f32x2 %0, %1, %2;" : "=l"(d) : "l"(a), "l"(b)); return d;
}

// ---- scratch (no allocations allowed) ----
__device__ float g_qkv [ROWS * QKV_F];             // [B,N,3*C]
__device__ float g_q   [BQ*NHEAD*NSEQ*HDIM];       // [B,H,N,D] rmsnorm+rope+scale
__device__ float g_k   [BQ*NHEAD*NSEQ*HDIM];       // [B,H,N,D] rmsnorm+rope
__device__ float g_attn[ROWS * DIMC];              // [B,N,C]

// ============================================================
// GEMM (NT): C[m,n] = sum_k A[m,k]*B[n,k] (+bias[n])
// 128x128x8 tile, 8x8 per thread, f32x2 packed accumulation over n.
// ============================================================
__global__ __launch_bounds__(256) void gemm_nt(
    const float* __restrict__ A, const float* __restrict__ B,
    const float* __restrict__ bias, float* __restrict__ C,
    int M, int N, int K)
{
    __shared__ __align__(16) float As[8][132];
    __shared__ __align__(16) float Bs[8][132];

    const int tid  = threadIdx.x;
    const int tx   = tid & 15;          // n sub-block
    const int ty   = tid >> 4;          // m sub-block
    const int lrow = tid >> 1;          // 0..127
    const int lcol = (tid & 1) << 2;    // 0 or 4

    const float* Ap = A + (size_t)(blockIdx.y * 128 + lrow) * K + lcol;
    const float* Bp = B + (size_t)(blockIdx.x * 128 + lrow) * K + lcol;

    u64t acc2[8][4];
#pragma unroll
    for (int i = 0; i < 8; i++)
#pragma unroll
        for (int j = 0; j < 4; j++) acc2[i][j] = 0ull;

    float4 av = *(const float4*)Ap;
    float4 bv = *(const float4*)Bp;

    for (int k0 = 0; k0 < K; k0 += 8) {
        __syncthreads();
        As[lcol + 0][lrow] = av.x; As[lcol + 1][lrow] = av.y;
        As[lcol + 2][lrow] = av.z; As[lcol + 3][lrow] = av.w;
        Bs[lcol + 0][lrow] = bv.x; Bs[lcol + 1][lrow] = bv.y;
        Bs[lcol + 2][lrow] = bv.z; Bs[lcol + 3][lrow] = bv.w;
        __syncthreads();

        int kn = (k0 + 8 < K) ? (k0 + 8) : 0;     // prefetch next tile
        av = *(const float4*)(Ap + kn);
        bv = *(const float4*)(Bp + kn);

#pragma unroll
        for (int kk = 0; kk < 8; kk++) {
            float4 a0 = *(const float4*)&As[kk][ty * 8];
            float4 a1 = *(const float4*)&As[kk][ty * 8 + 4];
            const u64t* b2p = (const u64t*)&Bs[kk][tx * 8];
            u64t b2[4];
#pragma unroll
            for (int j = 0; j < 4; j++) b2[j] = b2p[j];
            float a[8] = {a0.x,a0.y,a0.z,a0.w,a1.x,a1.y,a1.z,a1.w};
#pragma unroll
            for (int i = 0; i < 8; i++) {
                u64t ad = pack2(a[i], a[i]);
#pragma unroll
                for (int j = 0; j < 4; j++)
                    acc2[i][j] = fma2(ad, b2[j], acc2[i][j]);
            }
        }
    }

    const int crow = blockIdx.y * 128 + ty * 8;
    const int ccol = blockIdx.x * 128 + tx * 8;
#pragma unroll
    for (int i = 0; i < 8; i++) {
        float c[8];
#pragma unroll
        for (int j = 0; j < 4; j++) unpack2(acc2[i][j], c[2*j], c[2*j+1]);
        if (bias) {
#pragma unroll
            for (int j = 0; j < 8; j++) c[j] += bias[ccol + j];
        }
        *(float4*)&C[(size_t)(crow + i) * N + ccol]     = make_float4(c[0],c[1],c[2],c[3]);
        *(float4*)&C[(size_t)(crow + i) * N + ccol + 4] = make_float4(c[4],c[5],c[6],c[7]);
    }
}

// ============================================================
// RMSNorm + rotary for q and k. One warp per (sel,b,h,n) row.
// ============================================================
__global__ __launch_bounds__(256) void rms_rot_kernel(
    const float* __restrict__ qkv, const float* __restrict__ pos,
    const float* __restrict__ qw, const float* __restrict__ kw,
    float* __restrict__ qout, float* __restrict__ kout)
{
    int wg   = blockIdx.x * (blockDim.x >> 5) + (threadIdx.x >> 5);
    int lane = threadIdx.x & 31;
    int n   =  wg        & (NSEQ - 1);
    int h   = (wg >> 11) & (NHEAD - 1);
    int b   = (wg >> 15) & 1;
    int sel =  wg >> 16;                     // 0 = q, 1 = k

    const float* src = qkv + (size_t)(b * NSEQ + n) * QKV_F + sel * DIMC + h * HDIM + 2 * lane;
    float2 v = *(const float2*)src;
    float ss = v.x * v.x + v.y * v.y;
#pragma unroll
    for (int o = 16; o; o >>= 1) ss += __shfl_xor_sync(0xffffffffu, ss, o);
    float r = rsqrtf(ss * (1.f / HDIM) + 1e-6f);

    const float* w = sel ? kw : qw;
    float xr = v.x * r * w[2 * lane];
    float xi = v.y * r * w[2 * lane + 1];

    float ang = pos[n * (HDIM / 2) + lane];
    float sn, cs;
    __sincosf(ang, &sn, &cs);
    float orr = xr * cs - xi * sn;
    float oi  = xr * sn + xi * cs;
    if (!sel) { orr *= 0.125f; oi *= 0.125f; }   // fold softmax scale into q

    float* dst = (sel ? kout : qout) +
                 (size_t)((b * NHEAD + h) * NSEQ + n) * HDIM + 2 * lane;
    *(float2*)dst = make_float2(orr, oi);
}

// ============================================================
// Flash attention (fp32, non-causal), f32x2 packed math.
// 1 query row / thread, 128 rows / CTA, 32-key smem tiles.
// ============================================================
__global__ __launch_bounds__(128) void attn_kernel(
    const float* __restrict__ Q, const float* __restrict__ Kt,
    const float* __restrict__ QKV, float* __restrict__ Out)
{
    __shared__ __align__(16) float ks[32 * HDIM];
    __shared__ __align__(16) float vs[32 * HDIM];

    const int tid = threadIdx.x;
    const int b = blockIdx.z, h = blockIdx.y;
    const int m = blockIdx.x * 128 + tid;

    const float* qrow = Q + ((size_t)((b * NHEAD + h) * NSEQ) + m) * HDIM;
    u64t q2[32];
#pragma unroll
    for (int i = 0; i < 32; i++) q2[i] = ((const u64t*)qrow)[i];

    u64t o2[32];
#pragma unroll
    for (int i = 0; i < 32; i++) o2[i] = 0ull;
    float mval = -1e30f, l = 0.f;

    const float* kbase = Kt + (size_t)((b * NHEAD + h) * NSEQ) * HDIM;
    const float* vbase = QKV + (size_t)b * NSEQ * QKV_F + 2 * DIMC + h * HDIM;

    for (int j0 = 0; j0 < NSEQ; j0 += 32) {
        const float4* ksrc = (const float4*)(kbase + (size_t)j0 * HDIM);
#pragma unroll
        for (int i = 0; i < 4; i++) ((float4*)ks)[tid + i * 128] = ksrc[tid + i * 128];
#pragma unroll
        for (int i = 0; i < 4; i++) {
            int f = tid + i * 128;            // float4 index 0..511
            int r = f >> 4, c = f & 15;
            ((float4*)vs)[f] = *(const float4*)(vbase + (size_t)(j0 + r) * QKV_F + c * 4);
        }
        __syncthreads();

        float s[32];
#pragma unroll
        for (int j = 0; j < 32; j++) {
            const u64t* kr2 = (const u64t*)(ks + j * HDIM);
            u64t acc = 0ull;
#pragma unroll
            for (int i = 0; i < 32; i++)
                acc = fma2(q2[i], kr2[i], acc);
            float lo, hi; unpack2(acc, lo, hi);
            s[j] = lo + hi;
        }

        float tmax = mval;
#pragma unroll
        for (int j = 0; j < 32; j++) tmax = fmaxf(tmax, s[j]);
        float corr = __expf(mval - tmax);
        mval = tmax;
        l *= corr;
        u64t corr2 = pack2(corr, corr);
#pragma unroll
        for (int i = 0; i < 32; i++) o2[i] = mul2(o2[i], corr2);

#pragma unroll
        for (int j = 0; j < 32; j++) {
            float p = __expf(s[j] - mval);
            l += p;
            u64t p2 = pack2(p, p);
            const u64t* vr2 = (const u64t*)(vs + j * HDIM);
#pragma unroll
            for (int i = 0; i < 32; i++)
                o2[i] = fma2(p2, vr2[i], o2[i]);
        }
        __syncthreads();
    }

    float inv = 1.f / l;
    u64t inv2 = pack2(inv, inv);
    u64t* dst = (u64t*)(Out + (size_t)(b * NSEQ + m) * DIMC + h * HDIM);
#pragma unroll
    for (int i = 0; i < 32; i++)
        dst[i] = mul2(o2[i], inv2);
}

// ============================================================
extern "C" void kernel_launch(void* const* d_in, const int* in_sizes, int n_in,
                              void* d_out, int out_size)
{
    const float* x      = (const float*)d_in[0];
    const float* pos    = (const float*)d_in[1];
    const float* qkv_w  = (const float*)d_in[2];
    const float* qnw    = (const float*)d_in[3];
    const float* knw    = (const float*)d_in[4];
    const float* proj_w = (const float*)d_in[5];
    const float* proj_b = (const float*)d_in[6];
    float* out = (float*)d_out;

    float *qkv, *qb, *kb, *attn;
    cudaGetSymbolAddress((void**)&qkv,  g_qkv);
    cudaGetSymbolAddress((void**)&qb,   g_q);
    cudaGetSymbolAddress((void**)&kb,   g_k);
    cudaGetSymbolAddress((void**)&attn, g_attn);

    // 1) QKV projection: [4096,1024] x [3072,1024]^T -> [4096,3072]
    gemm_nt<<<dim3(QKV_F / 128, ROWS / 128), 256>>>(x, qkv_w, nullptr, qkv,
                                                    ROWS, QKV_F, DIMC);
    // 2) RMSNorm + rotary (q scaled by D^-0.5)
    rms_rot_kernel<<<(2 * BQ * NHEAD * NSEQ) / 8, 256>>>(qkv, pos, qnw, knw, qb, kb);
    // 3) Flash attention
    attn_kernel<<<dim3(NSEQ / 128, NHEAD, BQ), 128>>>(qb, kb, qkv, attn);
    // 4) Output projection + bias: [4096,1024] x [1024,1024]^T -> out
    gemm_nt<<<dim3(DIMC / 128, ROWS / 128), 256>>>(attn, proj_w, proj_b, out,
                                                   ROWS, DIMC, DIMC);
}

// round 6
// speedup vs baseline: 1.2704x; 1.2704x over previous
#include <cuda_runtime.h>
#include <cuda_bf16.h>
#include <math.h>
#include <stdint.h>

#define DIMC  1024
#define NHEAD 16
#define HDIM  64
#define BQ    2
#define NSEQ  2048
#define ROWS  (BQ*NSEQ)      // 4096
#define QKV_F (3*DIMC)       // 3072

// ---- scratch (no allocations allowed) ----
__device__ float g_qkv [ROWS * QKV_F];
__device__ float g_q   [BQ*NHEAD*NSEQ*HDIM];
__device__ float g_k   [BQ*NHEAD*NSEQ*HDIM];
__device__ float g_attn[ROWS * DIMC];
__device__ __nv_bfloat16 g_xhi[ROWS * DIMC];
__device__ __nv_bfloat16 g_xlo[ROWS * DIMC];
__device__ __nv_bfloat16 g_whi[QKV_F * DIMC];
__device__ __nv_bfloat16 g_wlo[QKV_F * DIMC];
__device__ __nv_bfloat16 g_phi[DIMC * DIMC];
__device__ __nv_bfloat16 g_plo[DIMC * DIMC];
__device__ __nv_bfloat16 g_ahi[ROWS * DIMC];
__device__ __nv_bfloat16 g_alo[ROWS * DIMC];

__device__ __forceinline__ uint32_t cvta_smem(const void* p) {
    uint32_t a;
    asm("{ .reg .u64 t; cvta.to.shared.u64 t, %1; cvt.u32.u64 %0, t; }" : "=r"(a) : "l"(p));
    return a;
}
__device__ __forceinline__ void cp16(uint32_t dst, const void* src) {
    asm volatile("cp.async.ca.shared.global [%0], [%1], 16;" :: "r"(dst), "l"(src));
}
__device__ __forceinline__ void cp_commit() {
    asm volatile("cp.async.commit_group;");
}
__device__ __forceinline__ void ldmx4(uint32_t& r0, uint32_t& r1, uint32_t& r2, uint32_t& r3,
                                      uint32_t addr) {
    asm volatile("ldmatrix.sync.aligned.m8n8.x4.shared.b16 {%0,%1,%2,%3}, [%4];"
                 : "=r"(r0), "=r"(r1), "=r"(r2), "=r"(r3) : "r"(addr));
}
__device__ __forceinline__ void mma16816(float& d0, float& d1, float& d2, float& d3,
                                         uint32_t a0, uint32_t a1, uint32_t a2, uint32_t a3,
                                         uint32_t b0, uint32_t b1) {
    asm volatile(
        "mma.sync.aligned.m16n8k16.row.col.f32.bf16.bf16.f32 "
        "{%0,%1,%2,%3}, {%4,%5,%6,%7}, {%8,%9}, {%0,%1,%2,%3};"
        : "+f"(d0), "+f"(d1), "+f"(d2), "+f"(d3)
        : "r"(a0), "r"(a1), "r"(a2), "r"(a3), "r"(b0), "r"(b1));
}

// ============================================================
// mma.sync bf16 GEMM (NT), 3-term compensated:
// C = sum_s A_s * B_s^T over segments s=0..2, each K=1024.
// CTA tile 128x128, BK=64 bf16 (128B rows, SW128 swizzle), 8 warps (2m x 4n),
// warp tile 64x32, cp.async double-buffered.
// ============================================================
#define KSEG 1024
#define NCHT 48                // 3 segments x 16 k-tiles of 64
#define STAGE 16384            // 128 rows x 128B per operand stage
#define SMEM_TOT (4*STAGE)     // A0,A1,B0,B1

__global__ __launch_bounds__(256, 2) void mma_gemm(
    const __nv_bfloat16* __restrict__ A0, const __nv_bfloat16* __restrict__ A1,
    const __nv_bfloat16* __restrict__ A2,
    const __nv_bfloat16* __restrict__ B0, const __nv_bfloat16* __restrict__ B1,
    const __nv_bfloat16* __restrict__ B2,
    float* __restrict__ C, const float* __restrict__ bias, int ldC)
{
    extern __shared__ char smem[];
    const uint32_t sA = cvta_smem(smem);
    const uint32_t sB = sA + 2 * STAGE;

    const int tid  = threadIdx.x;
    const int warp = tid >> 5;
    const int lane = tid & 31;
    const int wm   = warp >> 2;          // 0..1 : 64-row slab
    const int wn   = warp & 3;           // 0..3 : 32-col slab
    const int m0 = blockIdx.y * 128;
    const int n0 = blockIdx.x * 128;

    const __nv_bfloat16* Asegs[3] = {A0, A1, A2};
    const __nv_bfloat16* Bsegs[3] = {B0, B1, B2};

    // gmem->smem mapping for this thread (4 x 16B per operand per stage)
    const int lrow = tid >> 3;                 // 0..31 (+32*i)
    const int lch  = tid & 7;                  // 16B chunk in 128B row

    auto issue_tile = [&](int kt, int buf) {
        const int seg = kt >> 4;
        const int kc  = (kt & 15) * 64;
        const __nv_bfloat16* Ap = Asegs[seg];
        const __nv_bfloat16* Bp = Bsegs[seg];
#pragma unroll
        for (int i = 0; i < 4; i++) {
            int row = lrow + 32 * i;
            uint32_t soff = (uint32_t)(row * 128 + ((lch * 16) ^ ((row & 7) << 4)));
            cp16(sA + buf * STAGE + soff, Ap + (size_t)(m0 + row) * KSEG + kc + lch * 8);
            cp16(sB + buf * STAGE + soff, Bp + (size_t)(n0 + row) * KSEG + kc + lch * 8);
        }
        cp_commit();
    };

    float acc[4][4][4];
#pragma unroll
    for (int i = 0; i < 4; i++)
#pragma unroll
        for (int j = 0; j < 4; j++)
#pragma unroll
            for (int v = 0; v < 4; v++) acc[i][j][v] = 0.f;

    // precompute ldmatrix row addressing
    const int lrow16 = lane & 15;          // row within 16-row frag
    const int lchunk = lane >> 4;          // k 16B chunk (0/1)
    uint32_t aRow[4], aMask[4];
#pragma unroll
    for (int fi = 0; fi < 4; fi++) {
        int r = wm * 64 + fi * 16 + lrow16;
        aRow[fi]  = (uint32_t)(r * 128);
        aMask[fi] = (uint32_t)((r & 7) << 4);
    }
    uint32_t bRow[2], bMask[2];
#pragma unroll
    for (int nj = 0; nj < 2; nj++) {
        int r = wn * 32 + nj * 16 + lrow16;
        bRow[nj]  = (uint32_t)(r * 128);
        bMask[nj] = (uint32_t)((r & 7) << 4);
    }

    issue_tile(0, 0);

    for (int kt = 0; kt < NCHT; kt++) {
        const int buf = kt & 1;
        if (kt + 1 < NCHT) {
            issue_tile(kt + 1, buf ^ 1);
            asm volatile("cp.async.wait_group 1;");
        } else {
            asm volatile("cp.async.wait_group 0;");
        }
        __syncthreads();

        const uint32_t aBase = sA + buf * STAGE;
        const uint32_t bBase = sB + buf * STAGE;
#pragma unroll
        for (int ks = 0; ks < 4; ks++) {
            const uint32_t kb = (uint32_t)(ks * 32 + lchunk * 16);
            uint32_t a[4][4];
#pragma unroll
            for (int fi = 0; fi < 4; fi++)
                ldmx4(a[fi][0], a[fi][1], a[fi][2], a[fi][3],
                      aBase + aRow[fi] + (kb ^ aMask[fi]));
            uint32_t b[2][4];
#pragma unroll
            for (int nj = 0; nj < 2; nj++)
                ldmx4(b[nj][0], b[nj][1], b[nj][2], b[nj][3],
                      bBase + bRow[nj] + (kb ^ bMask[nj]));
#pragma unroll
            for (int fi = 0; fi < 4; fi++) {
#pragma unroll
                for (int nj = 0; nj < 2; nj++) {
                    mma16816(acc[fi][2*nj][0], acc[fi][2*nj][1],
                             acc[fi][2*nj][2], acc[fi][2*nj][3],
                             a[fi][0], a[fi][1], a[fi][2], a[fi][3],
                             b[nj][0], b[nj][2]);
                    mma16816(acc[fi][2*nj+1][0], acc[fi][2*nj+1][1],
                             acc[fi][2*nj+1][2], acc[fi][2*nj+1][3],
                             a[fi][0], a[fi][1], a[fi][2], a[fi][3],
                             b[nj][1], b[nj][3]);
                }
            }
        }
        __syncthreads();
    }

    // ---- epilogue ----
    const int mrow = m0 + wm * 64 + (lane >> 2);
    const int ncol = n0 + wn * 32 + (lane & 3) * 2;
#pragma unroll
    for (int fi = 0; fi < 4; fi++) {
#pragma unroll
        for (int nb = 0; nb < 4; nb++) {
            int r = mrow + fi * 16;
            int c = ncol + nb * 8;
            float b0 = 0.f, b1 = 0.f;
            if (bias) { b0 = bias[c]; b1 = bias[c + 1]; }
            *(float2*)&C[(size_t)r * ldC + c] =
                make_float2(acc[fi][nb][0] + b0, acc[fi][nb][1] + b1);
            *(float2*)&C[(size_t)(r + 8) * ldC + c] =
                make_float2(acc[fi][nb][2] + b0, acc[fi][nb][3] + b1);
        }
    }
}

// ============================================================
// fp32 -> bf16 hi/lo split
// ============================================================
__global__ __launch_bounds__(256) void split_kernel(
    const float* __restrict__ in, __nv_bfloat16* __restrict__ hi,
    __nv_bfloat16* __restrict__ lo, int n4)
{
    int i = blockIdx.x * blockDim.x + threadIdx.x;
    if (i >= n4) return;
    float4 v = ((const float4*)in)[i];
    __nv_bfloat16 h[4], l[4];
    float x[4] = {v.x, v.y, v.z, v.w};
#pragma unroll
    for (int j = 0; j < 4; j++) {
        h[j] = __float2bfloat16_rn(x[j]);
        l[j] = __float2bfloat16_rn(x[j] - __bfloat162float(h[j]));
    }
    ((uint2*)hi)[i] = *(const uint2*)h;
    ((uint2*)lo)[i] = *(const uint2*)l;
}

// ============================================================
// RMSNorm + rotary (one warp per row)
// ============================================================
__global__ __launch_bounds__(256) void rms_rot_kernel(
    const float* __restrict__ qkv, const float* __restrict__ pos,
    const float* __restrict__ qw, const float* __restrict__ kw,
    float* __restrict__ qout, float* __restrict__ kout)
{
    int wgi  = blockIdx.x * (blockDim.x >> 5) + (threadIdx.x >> 5);
    int lane = threadIdx.x & 31;
    int n   =  wgi        & (NSEQ - 1);
    int h   = (wgi >> 11) & (NHEAD - 1);
    int b   = (wgi >> 15) & 1;
    int sel =  wgi >> 16;

    const float* src = qkv + (size_t)(b * NSEQ + n) * QKV_F + sel * DIMC + h * HDIM + 2 * lane;
    float2 v = *(const float2*)src;
    float ss = v.x * v.x + v.y * v.y;
#pragma unroll
    for (int o = 16; o; o >>= 1) ss += __shfl_xor_sync(0xffffffffu, ss, o);
    float r = rsqrtf(ss * (1.f / HDIM) + 1e-6f);

    const float* w = sel ? kw : qw;
    float xr = v.x * r * w[2 * lane];
    float xi = v.y * r * w[2 * lane + 1];

    float ang = pos[n * (HDIM / 2) + lane];
    float sn, cs;
    __sincosf(ang, &sn, &cs);
    float orr = xr * cs - xi * sn;
    float oi  = xr * sn + xi * cs;
    if (!sel) { orr *= 0.125f; oi *= 0.125f; }

    float* dst = (sel ? kout : qout) +
                 (size_t)((b * NHEAD + h) * NSEQ + n) * HDIM + 2 * lane;
    *(float2*)dst = make_float2(orr, oi);
}

// ============================================================
// Flash attention (fp32 scalar, non-causal) — proven version
// ============================================================
__global__ __launch_bounds__(128) void attn_kernel(
    const float* __restrict__ Q, const float* __restrict__ Kt,
    const float* __restrict__ QKV, float* __restrict__ Out)
{
    __shared__ __align__(16) float ks[32 * HDIM];
    __shared__ __align__(16) float vs[32 * HDIM];

    const int tid = threadIdx.x;
    const int b = blockIdx.z, h = blockIdx.y;
    const int m = blockIdx.x * 128 + tid;

    const float* qrow = Q + ((size_t)((b * NHEAD + h) * NSEQ) + m) * HDIM;
    float4 q4[16];
#pragma unroll
    for (int i = 0; i < 16; i++) q4[i] = *(const float4*)(qrow + i * 4);

    float4 o4[16];
#pragma unroll
    for (int i = 0; i < 16; i++) o4[i] = make_float4(0.f, 0.f, 0.f, 0.f);
    float mval = -1e30f, l = 0.f;

    const float* kbase = Kt + (size_t)((b * NHEAD + h) * NSEQ) * HDIM;
    const float* vbase = QKV + (size_t)b * NSEQ * QKV_F + 2 * DIMC + h * HDIM;

    for (int j0 = 0; j0 < NSEQ; j0 += 32) {
        const float4* ksrc = (const float4*)(kbase + (size_t)j0 * HDIM);
#pragma unroll
        for (int i = 0; i < 4; i++) ((float4*)ks)[tid + i * 128] = ksrc[tid + i * 128];
#pragma unroll
        for (int i = 0; i < 4; i++) {
            int f = tid + i * 128;
            int r = f >> 4, c = f & 15;
            ((float4*)vs)[f] = *(const float4*)(vbase + (size_t)(j0 + r) * QKV_F + c * 4);
        }
        __syncthreads();

        float s[32];
#pragma unroll
        for (int j = 0; j < 32; j++) {
            const float4* kr4 = (const float4*)(ks + j * HDIM);
            float acc = 0.f;
#pragma unroll
            for (int i = 0; i < 16; i++) {
                float4 kv = kr4[i];
                acc = fmaf(q4[i].x, kv.x, acc);
                acc = fmaf(q4[i].y, kv.y, acc);
                acc = fmaf(q4[i].z, kv.z, acc);
                acc = fmaf(q4[i].w, kv.w, acc);
            }
            s[j] = acc;
        }

        float tmax = mval;
#pragma unroll
        for (int j = 0; j < 32; j++) tmax = fmaxf(tmax, s[j]);
        float corr = __expf(mval - tmax);
        mval = tmax;
        l *= corr;
#pragma unroll
        for (int i = 0; i < 16; i++) {
            o4[i].x *= corr; o4[i].y *= corr; o4[i].z *= corr; o4[i].w *= corr;
        }
#pragma unroll
        for (int j = 0; j < 32; j++) {
            float p = __expf(s[j] - mval);
            l += p;
            const float4* vr4 = (const float4*)(vs + j * HDIM);
#pragma unroll
            for (int i = 0; i < 16; i++) {
                float4 vv = vr4[i];
                o4[i].x = fmaf(p, vv.x, o4[i].x);
                o4[i].y = fmaf(p, vv.y, o4[i].y);
                o4[i].z = fmaf(p, vv.z, o4[i].z);
                o4[i].w = fmaf(p, vv.w, o4[i].w);
            }
        }
        __syncthreads();
    }

    float inv = 1.f / l;
    float* dst = Out + (size_t)(b * NSEQ + m) * DIMC + h * HDIM;
#pragma unroll
    for (int i = 0; i < 16; i++) {
        float4 v = o4[i];
        v.x *= inv; v.y *= inv; v.z *= inv; v.w *= inv;
        *(float4*)(dst + i * 4) = v;
    }
}

// ============================================================
extern "C" void kernel_launch(void* const* d_in, const int* in_sizes, int n_in,
                              void* d_out, int out_size)
{
    const float* x      = (const float*)d_in[0];
    const float* pos    = (const float*)d_in[1];
    const float* qkv_w  = (const float*)d_in[2];
    const float* qnw    = (const float*)d_in[3];
    const float* knw    = (const float*)d_in[4];
    const float* proj_w = (const float*)d_in[5];
    const float* proj_b = (const float*)d_in[6];
    float* out = (float*)d_out;

    float *qkv, *qb, *kb, *attn;
    __nv_bfloat16 *xhi, *xlo, *whi, *wlo, *phi, *plo, *ahi, *alo;
    cudaGetSymbolAddress((void**)&qkv,  g_qkv);
    cudaGetSymbolAddress((void**)&qb,   g_q);
    cudaGetSymbolAddress((void**)&kb,   g_k);
    cudaGetSymbolAddress((void**)&attn, g_attn);
    cudaGetSymbolAddress((void**)&xhi,  g_xhi);
    cudaGetSymbolAddress((void**)&xlo,  g_xlo);
    cudaGetSymbolAddress((void**)&whi,  g_whi);
    cudaGetSymbolAddress((void**)&wlo,  g_wlo);
    cudaGetSymbolAddress((void**)&phi,  g_phi);
    cudaGetSymbolAddress((void**)&plo,  g_plo);
    cudaGetSymbolAddress((void**)&ahi,  g_ahi);
    cudaGetSymbolAddress((void**)&alo,  g_alo);

    cudaFuncSetAttribute(mma_gemm, cudaFuncAttributeMaxDynamicSharedMemorySize, SMEM_TOT);

    // 0) bf16 hi/lo splits
    split_kernel<<<(ROWS * DIMC / 4 + 255) / 256, 256>>>(x, xhi, xlo, ROWS * DIMC / 4);
    split_kernel<<<(QKV_F * DIMC / 4 + 255) / 256, 256>>>(qkv_w, whi, wlo, QKV_F * DIMC / 4);
    split_kernel<<<(DIMC * DIMC / 4 + 255) / 256, 256>>>(proj_w, phi, plo, DIMC * DIMC / 4);

    // 1) QKV projection (tensor cores, 3-term)
    mma_gemm<<<dim3(QKV_F / 128, ROWS / 128), 256, SMEM_TOT>>>(
        xhi, xhi, xlo, whi, wlo, whi, qkv, nullptr, QKV_F);

    // 2) RMSNorm + rotary
    rms_rot_kernel<<<(2 * BQ * NHEAD * NSEQ) / 8, 256>>>(qkv, pos, qnw, knw, qb, kb);

    // 3) Flash attention (scalar fp32)
    attn_kernel<<<dim3(NSEQ / 128, NHEAD, BQ), 128>>>(qb, kb, qkv, attn);

    // 4) proj (tensor cores, 3-term) + bias
    split_kernel<<<(ROWS * DIMC / 4 + 255) / 256, 256>>>(attn, ahi, alo, ROWS * DIMC / 4);
    mma_gemm<<<dim3(DIMC / 128, ROWS / 128), 256, SMEM_TOT>>>(
        ahi, ahi, alo, phi, plo, phi, out, proj_b, DIMC);
}

// round 7
// speedup vs baseline: 1.9114x; 1.5046x over previous
#include <cuda_runtime.h>
#include <cuda_bf16.h>
#include <math.h>
#include <stdint.h>

#define DIMC  1024
#define NHEAD 16
#define HDIM  64
#define BQ    2
#define NSEQ  2048
#define ROWS  (BQ*NSEQ)      // 4096
#define QKV_F (3*DIMC)       // 3072

// ---- scratch (no allocations allowed) ----
__device__ float g_qkv [ROWS * QKV_F];
__device__ float g_q   [BQ*NHEAD*NSEQ*HDIM];
__device__ float g_k   [BQ*NHEAD*NSEQ*HDIM];
__device__ __nv_bfloat16 g_xhi[ROWS * DIMC];
__device__ __nv_bfloat16 g_xlo[ROWS * DIMC];
__device__ __nv_bfloat16 g_whi[QKV_F * DIMC];
__device__ __nv_bfloat16 g_wlo[QKV_F * DIMC];
__device__ __nv_bfloat16 g_phi[DIMC * DIMC];
__device__ __nv_bfloat16 g_plo[DIMC * DIMC];
__device__ __nv_bfloat16 g_ahi[ROWS * DIMC];
__device__ __nv_bfloat16 g_alo[ROWS * DIMC];

__device__ __forceinline__ uint32_t cvta_smem(const void* p) {
    uint32_t a;
    asm("{ .reg .u64 t; cvta.to.shared.u64 t, %1; cvt.u32.u64 %0, t; }" : "=r"(a) : "l"(p));
    return a;
}
__device__ __forceinline__ void cp16(uint32_t dst, const void* src) {
    asm volatile("cp.async.ca.shared.global [%0], [%1], 16;" :: "r"(dst), "l"(src));
}
__device__ __forceinline__ void cp_commit() {
    asm volatile("cp.async.commit_group;");
}
__device__ __forceinline__ void ldmx4(uint32_t& r0, uint32_t& r1, uint32_t& r2, uint32_t& r3,
                                      uint32_t addr) {
    asm volatile("ldmatrix.sync.aligned.m8n8.x4.shared.b16 {%0,%1,%2,%3}, [%4];"
                 : "=r"(r0), "=r"(r1), "=r"(r2), "=r"(r3) : "r"(addr));
}
__device__ __forceinline__ void mma16816(float& d0, float& d1, float& d2, float& d3,
                                         uint32_t a0, uint32_t a1, uint32_t a2, uint32_t a3,
                                         uint32_t b0, uint32_t b1) {
    asm volatile(
        "mma.sync.aligned.m16n8k16.row.col.f32.bf16.bf16.f32 "
        "{%0,%1,%2,%3}, {%4,%5,%6,%7}, {%8,%9}, {%0,%1,%2,%3};"
        : "+f"(d0), "+f"(d1), "+f"(d2), "+f"(d3)
        : "r"(a0), "r"(a1), "r"(a2), "r"(a3), "r"(b0), "r"(b1));
}

// ============================================================
// mma.sync bf16 GEMM (NT), 3-term compensated, 3-stage cp.async pipeline.
// C = sum_s A_s * B_s^T, s=0..2, each K=1024. CTA 128x128, BK=64,
// SW128 swizzle, 8 warps (2m x 4n), warp tile 64x32.
// ============================================================
#define KSEG 1024
#define NCHT 48                  // 3 segments x 16 k-tiles of 64
#define OPND 16384               // 128 rows x 128B
#define STAGEB (2*OPND)          // A + B per stage
#define SMEM_TOT (3*STAGEB)      // 3 stages = 96KB

template<int TAG>
__global__ __launch_bounds__(256, 2) void mma_gemm(
    const __nv_bfloat16* __restrict__ A0, const __nv_bfloat16* __restrict__ A1,
    const __nv_bfloat16* __restrict__ A2,
    const __nv_bfloat16* __restrict__ B0, const __nv_bfloat16* __restrict__ B1,
    const __nv_bfloat16* __restrict__ B2,
    float* __restrict__ C, const float* __restrict__ bias, int ldC)
{
    extern __shared__ char smem[];
    const uint32_t sbase = cvta_smem(smem);

    const int tid  = threadIdx.x;
    const int warp = tid >> 5;
    const int lane = tid & 31;
    const int wm   = warp >> 2;
    const int wn   = warp & 3;
    const int m0 = blockIdx.y * 128;
    const int n0 = blockIdx.x * 128;

    const __nv_bfloat16* Asegs[3] = {A0, A1, A2};
    const __nv_bfloat16* Bsegs[3] = {B0, B1, B2};

    const int lrow = tid >> 3;                 // 0..31 (+32*i)
    const int lch  = tid & 7;                  // 16B chunk in 128B row

    auto issue_tile = [&](int kt, int stg) {
        const int seg = kt >> 4;
        const int kc  = (kt & 15) * 64;
        const __nv_bfloat16* Ap = Asegs[seg];
        const __nv_bfloat16* Bp = Bsegs[seg];
        const uint32_t base = sbase + stg * STAGEB;
#pragma unroll
        for (int i = 0; i < 4; i++) {
            int row = lrow + 32 * i;
            uint32_t soff = (uint32_t)(row * 128 + ((lch * 16) ^ ((row & 7) << 4)));
            cp16(base + soff,        Ap + (size_t)(m0 + row) * KSEG + kc + lch * 8);
            cp16(base + OPND + soff, Bp + (size_t)(n0 + row) * KSEG + kc + lch * 8);
        }
        cp_commit();
    };

    float acc[4][4][4];
#pragma unroll
    for (int i = 0; i < 4; i++)
#pragma unroll
        for (int j = 0; j < 4; j++)
#pragma unroll
            for (int v = 0; v < 4; v++) acc[i][j][v] = 0.f;

    const int lrow16 = lane & 15;
    const int lchunk = lane >> 4;
    uint32_t aRow[4], aMask[4];
#pragma unroll
    for (int fi = 0; fi < 4; fi++) {
        int r = wm * 64 + fi * 16 + lrow16;
        aRow[fi]  = (uint32_t)(r * 128);
        aMask[fi] = (uint32_t)((r & 7) << 4);
    }
    uint32_t bRow[2], bMask[2];
#pragma unroll
    for (int nj = 0; nj < 2; nj++) {
        int r = wn * 32 + nj * 16 + lrow16;
        bRow[nj]  = (uint32_t)(r * 128 + OPND);
        bMask[nj] = (uint32_t)((r & 7) << 4);
    }

    issue_tile(0, 0);
    issue_tile(1, 1);

    for (int kt = 0; kt < NCHT; kt++) {
        const int stg = kt - (kt / 3) * 3;
        if (kt + 1 < NCHT) asm volatile("cp.async.wait_group 1;");
        else               asm volatile("cp.async.wait_group 0;");
        __syncthreads();
        if (kt + 2 < NCHT) issue_tile(kt + 2, (kt + 2) - ((kt + 2) / 3) * 3);

        const uint32_t base = sbase + stg * STAGEB;
#pragma unroll
        for (int ks = 0; ks < 4; ks++) {
            const uint32_t kb = (uint32_t)(ks * 32 + lchunk * 16);
            uint32_t a[4][4];
#pragma unroll
            for (int fi = 0; fi < 4; fi++)
                ldmx4(a[fi][0], a[fi][1], a[fi][2], a[fi][3],
                      base + aRow[fi] + (kb ^ aMask[fi]));
            uint32_t b[2][4];
#pragma unroll
            for (int nj = 0; nj < 2; nj++)
                ldmx4(b[nj][0], b[nj][1], b[nj][2], b[nj][3],
                      base + bRow[nj] + (kb ^ bMask[nj]));
#pragma unroll
            for (int fi = 0; fi < 4; fi++) {
#pragma unroll
                for (int nj = 0; nj < 2; nj++) {
                    mma16816(acc[fi][2*nj][0], acc[fi][2*nj][1],
                             acc[fi][2*nj][2], acc[fi][2*nj][3],
                             a[fi][0], a[fi][1], a[fi][2], a[fi][3],
                             b[nj][0], b[nj][2]);
                    mma16816(acc[fi][2*nj+1][0], acc[fi][2*nj+1][1],
                             acc[fi][2*nj+1][2], acc[fi][2*nj+1][3],
                             a[fi][0], a[fi][1], a[fi][2], a[fi][3],
                             b[nj][1], b[nj][3]);
                }
            }
        }
    }

    const int mrow = m0 + wm * 64 + (lane >> 2);
    const int ncol = n0 + wn * 32 + (lane & 3) * 2;
#pragma unroll
    for (int fi = 0; fi < 4; fi++) {
#pragma unroll
        for (int nb = 0; nb < 4; nb++) {
            int r = mrow + fi * 16;
            int c = ncol + nb * 8;
            float b0 = 0.f, b1 = 0.f;
            if (bias) { b0 = bias[c]; b1 = bias[c + 1]; }
            *(float2*)&C[(size_t)r * ldC + c] =
                make_float2(acc[fi][nb][0] + b0, acc[fi][nb][1] + b1);
            *(float2*)&C[(size_t)(r + 8) * ldC + c] =
                make_float2(acc[fi][nb][2] + b0, acc[fi][nb][3] + b1);
        }
    }
}

// ============================================================
// fp32 -> bf16 hi/lo split
// ============================================================
__global__ __launch_bounds__(256) void split_kernel(
    const float* __restrict__ in, __nv_bfloat16* __restrict__ hi,
    __nv_bfloat16* __restrict__ lo, int n4)
{
    int i = blockIdx.x * blockDim.x + threadIdx.x;
    if (i >= n4) return;
    float4 v = ((const float4*)in)[i];
    __nv_bfloat16 h[4], l[4];
    float x[4] = {v.x, v.y, v.z, v.w};
#pragma unroll
    for (int j = 0; j < 4; j++) {
        h[j] = __float2bfloat16_rn(x[j]);
        l[j] = __float2bfloat16_rn(x[j] - __bfloat162float(h[j]));
    }
    ((uint2*)hi)[i] = *(const uint2*)h;
    ((uint2*)lo)[i] = *(const uint2*)l;
}

// ============================================================
// RMSNorm + rotary (one warp per row)
// ============================================================
__global__ __launch_bounds__(256) void rms_rot_kernel(
    const float* __restrict__ qkv, const float* __restrict__ pos,
    const float* __restrict__ qw, const float* __restrict__ kw,
    float* __restrict__ qout, float* __restrict__ kout)
{
    int wgi  = blockIdx.x * (blockDim.x >> 5) + (threadIdx.x >> 5);
    int lane = threadIdx.x & 31;
    int n   =  wgi        & (NSEQ - 1);
    int h   = (wgi >> 11) & (NHEAD - 1);
    int b   = (wgi >> 15) & 1;
    int sel =  wgi >> 16;

    const float* src = qkv + (size_t)(b * NSEQ + n) * QKV_F + sel * DIMC + h * HDIM + 2 * lane;
    float2 v = *(const float2*)src;
    float ss = v.x * v.x + v.y * v.y;
#pragma unroll
    for (int o = 16; o; o >>= 1) ss += __shfl_xor_sync(0xffffffffu, ss, o);
    float r = rsqrtf(ss * (1.f / HDIM) + 1e-6f);

    const float* w = sel ? kw : qw;
    float xr = v.x * r * w[2 * lane];
    float xi = v.y * r * w[2 * lane + 1];

    float ang = pos[n * (HDIM / 2) + lane];
    float sn, cs;
    __sincosf(ang, &sn, &cs);
    float orr = xr * cs - xi * sn;
    float oi  = xr * sn + xi * cs;
    if (!sel) { orr *= 0.125f; oi *= 0.125f; }

    float* dst = (sel ? kout : qout) +
                 (size_t)((b * NHEAD + h) * NSEQ + n) * HDIM + 2 * lane;
    *(float2*)dst = make_float2(orr, oi);
}

// ============================================================
// Flash attention (fp32 scalar) with fused bf16 hi/lo output split.
// ============================================================
__global__ __launch_bounds__(128) void attn_kernel(
    const float* __restrict__ Q, const float* __restrict__ Kt,
    const float* __restrict__ QKV,
    __nv_bfloat16* __restrict__ OutHi, __nv_bfloat16* __restrict__ OutLo)
{
    __shared__ __align__(16) float ks[32 * HDIM];
    __shared__ __align__(16) float vs[32 * HDIM];

    const int tid = threadIdx.x;
    const int b = blockIdx.z, h = blockIdx.y;
    const int m = blockIdx.x * 128 + tid;

    const float* qrow = Q + ((size_t)((b * NHEAD + h) * NSEQ) + m) * HDIM;
    float4 q4[16];
#pragma unroll
    for (int i = 0; i < 16; i++) q4[i] = *(const float4*)(qrow + i * 4);

    float4 o4[16];
#pragma unroll
    for (int i = 0; i < 16; i++) o4[i] = make_float4(0.f, 0.f, 0.f, 0.f);
    float mval = -1e30f, l = 0.f;

    const float* kbase = Kt + (size_t)((b * NHEAD + h) * NSEQ) * HDIM;
    const float* vbase = QKV + (size_t)b * NSEQ * QKV_F + 2 * DIMC + h * HDIM;

    for (int j0 = 0; j0 < NSEQ; j0 += 32) {
        const float4* ksrc = (const float4*)(kbase + (size_t)j0 * HDIM);
#pragma unroll
        for (int i = 0; i < 4; i++) ((float4*)ks)[tid + i * 128] = ksrc[tid + i * 128];
#pragma unroll
        for (int i = 0; i < 4; i++) {
            int f = tid + i * 128;
            int r = f >> 4, c = f & 15;
            ((float4*)vs)[f] = *(const float4*)(vbase + (size_t)(j0 + r) * QKV_F + c * 4);
        }
        __syncthreads();

        float s[32];
#pragma unroll
        for (int j = 0; j < 32; j++) {
            const float4* kr4 = (const float4*)(ks + j * HDIM);
            float acc = 0.f;
#pragma unroll
            for (int i = 0; i < 16; i++) {
                float4 kv = kr4[i];
                acc = fmaf(q4[i].x, kv.x, acc);
                acc = fmaf(q4[i].y, kv.y, acc);
                acc = fmaf(q4[i].z, kv.z, acc);
                acc = fmaf(q4[i].w, kv.w, acc);
            }
            s[j] = acc;
        }

        float tmax = mval;
#pragma unroll
        for (int j = 0; j < 32; j++) tmax = fmaxf(tmax, s[j]);
        float corr = __expf(mval - tmax);
        mval = tmax;
        l *= corr;
#pragma unroll
        for (int i = 0; i < 16; i++) {
            o4[i].x *= corr; o4[i].y *= corr; o4[i].z *= corr; o4[i].w *= corr;
        }
#pragma unroll
        for (int j = 0; j < 32; j++) {
            float p = __expf(s[j] - mval);
            l += p;
            const float4* vr4 = (const float4*)(vs + j * HDIM);
#pragma unroll
            for (int i = 0; i < 16; i++) {
                float4 vv = vr4[i];
                o4[i].x = fmaf(p, vv.x, o4[i].x);
                o4[i].y = fmaf(p, vv.y, o4[i].y);
                o4[i].z = fmaf(p, vv.z, o4[i].z);
                o4[i].w = fmaf(p, vv.w, o4[i].w);
            }
        }
        __syncthreads();
    }

    // fused epilogue: o/l -> bf16 hi + lo
    float inv = 1.f / l;
    uint32_t hp[32], lp[32];
#pragma unroll
    for (int i = 0; i < 16; i++) {
        float vals[4] = {o4[i].x * inv, o4[i].y * inv, o4[i].z * inv, o4[i].w * inv};
#pragma unroll
        for (int p2 = 0; p2 < 2; p2++) {
            __nv_bfloat16 h0 = __float2bfloat16_rn(vals[2*p2]);
            __nv_bfloat16 h1 = __float2bfloat16_rn(vals[2*p2+1]);
            __nv_bfloat16 l0 = __float2bfloat16_rn(vals[2*p2]   - __bfloat162float(h0));
            __nv_bfloat16 l1 = __float2bfloat16_rn(vals[2*p2+1] - __bfloat162float(h1));
            hp[i*2+p2] = (uint32_t)*(uint16_t*)&h0 | ((uint32_t)*(uint16_t*)&h1 << 16);
            lp[i*2+p2] = (uint32_t)*(uint16_t*)&l0 | ((uint32_t)*(uint16_t*)&l1 << 16);
        }
    }
    size_t dofs = (size_t)(b * NSEQ + m) * DIMC + h * HDIM;
#pragma unroll
    for (int j = 0; j < 8; j++) {
        ((uint4*)(OutHi + dofs))[j] = ((const uint4*)hp)[j];
        ((uint4*)(OutLo + dofs))[j] = ((const uint4*)lp)[j];
    }
}

// ============================================================
extern "C" void kernel_launch(void* const* d_in, const int* in_sizes, int n_in,
                              void* d_out, int out_size)
{
    const float* x      = (const float*)d_in[0];
    const float* pos    = (const float*)d_in[1];
    const float* qkv_w  = (const float*)d_in[2];
    const float* qnw    = (const float*)d_in[3];
    const float* knw    = (const float*)d_in[4];
    const float* proj_w = (const float*)d_in[5];
    const float* proj_b = (const float*)d_in[6];
    float* out = (float*)d_out;

    float *qkv, *qb, *kb;
    __nv_bfloat16 *xhi, *xlo, *whi, *wlo, *phi, *plo, *ahi, *alo;
    cudaGetSymbolAddress((void**)&qkv,  g_qkv);
    cudaGetSymbolAddress((void**)&qb,   g_q);
    cudaGetSymbolAddress((void**)&kb,   g_k);
    cudaGetSymbolAddress((void**)&xhi,  g_xhi);
    cudaGetSymbolAddress((void**)&xlo,  g_xlo);
    cudaGetSymbolAddress((void**)&whi,  g_whi);
    cudaGetSymbolAddress((void**)&wlo,  g_wlo);
    cudaGetSymbolAddress((void**)&phi,  g_phi);
    cudaGetSymbolAddress((void**)&plo,  g_plo);
    cudaGetSymbolAddress((void**)&ahi,  g_ahi);
    cudaGetSymbolAddress((void**)&alo,  g_alo);

    cudaFuncSetAttribute(mma_gemm<0>, cudaFuncAttributeMaxDynamicSharedMemorySize, SMEM_TOT);
    cudaFuncSetAttribute(mma_gemm<1>, cudaFuncAttributeMaxDynamicSharedMemorySize, SMEM_TOT);

    // 0) bf16 hi/lo splits of inputs
    split_kernel<<<(ROWS * DIMC / 4 + 255) / 256, 256>>>(x, xhi, xlo, ROWS * DIMC / 4);
    split_kernel<<<(QKV_F * DIMC / 4 + 255) / 256, 256>>>(qkv_w, whi, wlo, QKV_F * DIMC / 4);
    split_kernel<<<(DIMC * DIMC / 4 + 255) / 256, 256>>>(proj_w, phi, plo, DIMC * DIMC / 4);

    // 1) QKV projection (tensor cores, 3-term)
    mma_gemm<0><<<dim3(QKV_F / 128, ROWS / 128), 256, SMEM_TOT>>>(
        xhi, xhi, xlo, whi, wlo, whi, qkv, nullptr, QKV_F);

    // 2) RMSNorm + rotary
    rms_rot_kernel<<<(2 * BQ * NHEAD * NSEQ) / 8, 256>>>(qkv, pos, qnw, knw, qb, kb);

    // 3) Flash attention (scalar fp32) + fused bf16 split of output
    attn_kernel<<<dim3(NSEQ / 128, NHEAD, BQ), 128>>>(qb, kb, qkv, ahi, alo);

    // 4) proj (tensor cores, 3-term) + bias
    mma_gemm<1><<<dim3(DIMC / 128, ROWS / 128), 256, SMEM_TOT>>>(
        ahi, ahi, alo, phi, plo, phi, out, proj_b, DIMC);
}

// round 9
// speedup vs baseline: 4.0638x; 2.1260x over previous
#include <cuda_runtime.h>
#include <cuda_bf16.h>
#include <math.h>
#include <stdint.h>

#define DIMC  1024
#define NHEAD 16
#define HDIM  64
#define BQ    2
#define NSEQ  2048
#define ROWS  (BQ*NSEQ)      // 4096
#define QKV_F (3*DIMC)       // 3072
#define L2E   1.4426950408889634f

// ---- scratch (no allocations allowed) ----
__device__ float g_qkv [ROWS * QKV_F];
__device__ __nv_bfloat16 g_xhi[ROWS * DIMC];
__device__ __nv_bfloat16 g_xlo[ROWS * DIMC];
__device__ __nv_bfloat16 g_whi[QKV_F * DIMC];
__device__ __nv_bfloat16 g_wlo[QKV_F * DIMC];
__device__ __nv_bfloat16 g_phi[DIMC * DIMC];
__device__ __nv_bfloat16 g_plo[DIMC * DIMC];
__device__ __nv_bfloat16 g_ahi[ROWS * DIMC];
__device__ __nv_bfloat16 g_alo[ROWS * DIMC];
// [B,H,N,D] bf16 hi/lo operands for attention
__device__ __nv_bfloat16 g_qhi[ROWS * DIMC];
__device__ __nv_bfloat16 g_qlo[ROWS * DIMC];
__device__ __nv_bfloat16 g_khi[ROWS * DIMC];
__device__ __nv_bfloat16 g_klo[ROWS * DIMC];
__device__ __nv_bfloat16 g_vhi[ROWS * DIMC];
__device__ __nv_bfloat16 g_vlo[ROWS * DIMC];

__device__ __forceinline__ uint32_t cvta_smem(const void* p) {
    uint32_t a;
    asm("{ .reg .u64 t; cvta.to.shared.u64 t, %1; cvt.u32.u64 %0, t; }" : "=r"(a) : "l"(p));
    return a;
}
__device__ __forceinline__ void cp16(uint32_t dst, const void* src) {
    asm volatile("cp.async.ca.shared.global [%0], [%1], 16;" :: "r"(dst), "l"(src));
}
__device__ __forceinline__ void cp_commit() {
    asm volatile("cp.async.commit_group;");
}
__device__ __forceinline__ void ldmx4(uint32_t& r0, uint32_t& r1, uint32_t& r2, uint32_t& r3,
                                      uint32_t addr) {
    asm volatile("ldmatrix.sync.aligned.m8n8.x4.shared.b16 {%0,%1,%2,%3}, [%4];"
                 : "=r"(r0), "=r"(r1), "=r"(r2), "=r"(r3) : "r"(addr));
}
__device__ __forceinline__ void ldmx4t(uint32_t& r0, uint32_t& r1, uint32_t& r2, uint32_t& r3,
                                       uint32_t addr) {
    asm volatile("ldmatrix.sync.aligned.m8n8.x4.trans.shared.b16 {%0,%1,%2,%3}, [%4];"
                 : "=r"(r0), "=r"(r1), "=r"(r2), "=r"(r3) : "r"(addr));
}
__device__ __forceinline__ void mma16816(float* d,
                                         uint32_t a0, uint32_t a1, uint32_t a2, uint32_t a3,
                                         uint32_t b0, uint32_t b1) {
    asm volatile(
        "mma.sync.aligned.m16n8k16.row.col.f32.bf16.bf16.f32 "
        "{%0,%1,%2,%3}, {%4,%5,%6,%7}, {%8,%9}, {%0,%1,%2,%3};"
        : "+f"(d[0]), "+f"(d[1]), "+f"(d[2]), "+f"(d[3])
        : "r"(a0), "r"(a1), "r"(a2), "r"(a3), "r"(b0), "r"(b1));
}
// exp2 on the FMA pipe: y <= 0, clamped; magic-round + deg-5 poly + exponent add
__device__ __forceinline__ float exp2f_fast(float y) {
    y = fmaxf(y, -120.f);
    float t  = y + 12582912.f;           // 1.5*2^23
    float fl = t - 12582912.f;
    float fr = y - fl;                   // [-0.5, 0.5]
    float p = 0.0013333558f;
    p = fmaf(p, fr, 0.0096181291f);
    p = fmaf(p, fr, 0.0555041087f);
    p = fmaf(p, fr, 0.2402265069f);
    p = fmaf(p, fr, 0.6931471806f);
    p = fmaf(p, fr, 1.0f);
    int e = __float_as_int(t) << 23;     // int(y) << 23 (mod 2^32)
    return __int_as_float(__float_as_int(p) + e);
}

// ============================================================
// mma.sync bf16 GEMM (NT), 3-term compensated, 3-stage cp.async pipeline.
// ============================================================
#define KSEG 1024
#define NCHT 48
#define OPND 16384
#define STAGEB (2*OPND)
#define SMEM_TOT (3*STAGEB)

template<int TAG>
__global__ __launch_bounds__(256, 2) void mma_gemm(
    const __nv_bfloat16* __restrict__ A0, const __nv_bfloat16* __restrict__ A1,
    const __nv_bfloat16* __restrict__ A2,
    const __nv_bfloat16* __restrict__ B0, const __nv_bfloat16* __restrict__ B1,
    const __nv_bfloat16* __restrict__ B2,
    float* __restrict__ C, const float* __restrict__ bias, int ldC)
{
    extern __shared__ char smem[];
    const uint32_t sbase = cvta_smem(smem);

    const int tid  = threadIdx.x;
    const int warp = tid >> 5;
    const int lane = tid & 31;
    const int wm   = warp >> 2;
    const int wn   = warp & 3;
    const int m0 = blockIdx.y * 128;
    const int n0 = blockIdx.x * 128;

    const __nv_bfloat16* Asegs[3] = {A0, A1, A2};
    const __nv_bfloat16* Bsegs[3] = {B0, B1, B2};

    const int lrow = tid >> 3;
    const int lch  = tid & 7;

    auto issue_tile = [&](int kt, int stg) {
        const int seg = kt >> 4;
        const int kc  = (kt & 15) * 64;
        const __nv_bfloat16* Ap = Asegs[seg];
        const __nv_bfloat16* Bp = Bsegs[seg];
        const uint32_t base = sbase + stg * STAGEB;
#pragma unroll
        for (int i = 0; i < 4; i++) {
            int row = lrow + 32 * i;
            uint32_t soff = (uint32_t)(row * 128 + ((lch * 16) ^ ((row & 7) << 4)));
            cp16(base + soff,        Ap + (size_t)(m0 + row) * KSEG + kc + lch * 8);
            cp16(base + OPND + soff, Bp + (size_t)(n0 + row) * KSEG + kc + lch * 8);
        }
        cp_commit();
    };

    float acc[4][4][4];
#pragma unroll
    for (int i = 0; i < 4; i++)
#pragma unroll
        for (int j = 0; j < 4; j++)
#pragma unroll
            for (int v = 0; v < 4; v++) acc[i][j][v] = 0.f;

    const int lrow16 = lane & 15;
    const int lchunk = lane >> 4;
    uint32_t aRow[4], aMask[4];
#pragma unroll
    for (int fi = 0; fi < 4; fi++) {
        int r = wm * 64 + fi * 16 + lrow16;
        aRow[fi]  = (uint32_t)(r * 128);
        aMask[fi] = (uint32_t)((r & 7) << 4);
    }
    uint32_t bRow[2], bMask[2];
#pragma unroll
    for (int nj = 0; nj < 2; nj++) {
        int r = wn * 32 + nj * 16 + lrow16;
        bRow[nj]  = (uint32_t)(r * 128 + OPND);
        bMask[nj] = (uint32_t)((r & 7) << 4);
    }

    issue_tile(0, 0);
    issue_tile(1, 1);

    for (int kt = 0; kt < NCHT; kt++) {
        const int stg = kt - (kt / 3) * 3;
        if (kt + 1 < NCHT) asm volatile("cp.async.wait_group 1;");
        else               asm volatile("cp.async.wait_group 0;");
        __syncthreads();
        if (kt + 2 < NCHT) issue_tile(kt + 2, (kt + 2) - ((kt + 2) / 3) * 3);

        const uint32_t base = sbase + stg * STAGEB;
#pragma unroll
        for (int ks = 0; ks < 4; ks++) {
            const uint32_t kb = (uint32_t)(ks * 32 + lchunk * 16);
            uint32_t a[4][4];
#pragma unroll
            for (int fi = 0; fi < 4; fi++)
                ldmx4(a[fi][0], a[fi][1], a[fi][2], a[fi][3],
                      base + aRow[fi] + (kb ^ aMask[fi]));
            uint32_t b[2][4];
#pragma unroll
            for (int nj = 0; nj < 2; nj++)
                ldmx4(b[nj][0], b[nj][1], b[nj][2], b[nj][3],
                      base + bRow[nj] + (kb ^ bMask[nj]));
#pragma unroll
            for (int fi = 0; fi < 4; fi++) {
#pragma unroll
                for (int nj = 0; nj < 2; nj++) {
                    mma16816(acc[fi][2*nj],   a[fi][0], a[fi][1], a[fi][2], a[fi][3],
                             b[nj][0], b[nj][2]);
                    mma16816(acc[fi][2*nj+1], a[fi][0], a[fi][1], a[fi][2], a[fi][3],
                             b[nj][1], b[nj][3]);
                }
            }
        }
    }

    const int mrow = m0 + wm * 64 + (lane >> 2);
    const int ncol = n0 + wn * 32 + (lane & 3) * 2;
#pragma unroll
    for (int fi = 0; fi < 4; fi++) {
#pragma unroll
        for (int nb = 0; nb < 4; nb++) {
            int r = mrow + fi * 16;
            int c = ncol + nb * 8;
            float b0 = 0.f, b1 = 0.f;
            if (bias) { b0 = bias[c]; b1 = bias[c + 1]; }
            *(float2*)&C[(size_t)r * ldC + c] =
                make_float2(acc[fi][nb][0] + b0, acc[fi][nb][1] + b1);
            *(float2*)&C[(size_t)(r + 8) * ldC + c] =
                make_float2(acc[fi][nb][2] + b0, acc[fi][nb][3] + b1);
        }
    }
}

// ============================================================
// fp32 -> bf16 hi/lo split
// ============================================================
__global__ __launch_bounds__(256) void split_kernel(
    const float* __restrict__ in, __nv_bfloat16* __restrict__ hi,
    __nv_bfloat16* __restrict__ lo, int n4)
{
    int i = blockIdx.x * blockDim.x + threadIdx.x;
    if (i >= n4) return;
    float4 v = ((const float4*)in)[i];
    __nv_bfloat16 h[4], l[4];
    float x[4] = {v.x, v.y, v.z, v.w};
#pragma unroll
    for (int j = 0; j < 4; j++) {
        h[j] = __float2bfloat16_rn(x[j]);
        l[j] = __float2bfloat16_rn(x[j] - __bfloat162float(h[j]));
    }
    ((uint2*)hi)[i] = *(const uint2*)h;
    ((uint2*)lo)[i] = *(const uint2*)l;
}

// ============================================================
// RMSNorm + rotary for q,k and raw split for v.
// One warp per (sel,b,h,n) row; writes bf16 hi/lo in [B,H,N,D].
// ============================================================
__global__ __launch_bounds__(256) void rms_rot_kernel(
    const float* __restrict__ qkv, const float* __restrict__ pos,
    const float* __restrict__ qw, const float* __restrict__ kw,
    __nv_bfloat16* __restrict__ qhi, __nv_bfloat16* __restrict__ qlo,
    __nv_bfloat16* __restrict__ khi, __nv_bfloat16* __restrict__ klo,
    __nv_bfloat16* __restrict__ vhi, __nv_bfloat16* __restrict__ vlo)
{
    int wgi  = blockIdx.x * (blockDim.x >> 5) + (threadIdx.x >> 5);
    int lane = threadIdx.x & 31;
    int n   =  wgi        & (NSEQ - 1);
    int h   = (wgi >> 11) & (NHEAD - 1);
    int b   = (wgi >> 15) & 1;
    int sel =  wgi >> 16;                     // 0=q, 1=k, 2=v

    const float* src = qkv + (size_t)(b * NSEQ + n) * QKV_F + sel * DIMC + h * HDIM + 2 * lane;
    float2 v = *(const float2*)src;

    float o0, o1;
    if (sel < 2) {
        float ss = v.x * v.x + v.y * v.y;
#pragma unroll
        for (int o = 16; o; o >>= 1) ss += __shfl_xor_sync(0xffffffffu, ss, o);
        float r = rsqrtf(ss * (1.f / HDIM) + 1e-6f);
        const float* w = sel ? kw : qw;
        float xr = v.x * r * w[2 * lane];
        float xi = v.y * r * w[2 * lane + 1];
        float ang = pos[n * (HDIM / 2) + lane];
        float sn, cs;
        __sincosf(ang, &sn, &cs);
        o0 = xr * cs - xi * sn;
        o1 = xr * sn + xi * cs;
        if (!sel) { o0 *= 0.125f; o1 *= 0.125f; }
    } else {
        o0 = v.x; o1 = v.y;
    }

    __nv_bfloat16* hi = (sel == 0) ? qhi : (sel == 1) ? khi : vhi;
    __nv_bfloat16* lo = (sel == 0) ? qlo : (sel == 1) ? klo : vlo;
    size_t dofs = (size_t)((b * NHEAD + h) * NSEQ + n) * HDIM + 2 * lane;
    __nv_bfloat162 hp = __floats2bfloat162_rn(o0, o1);
    __nv_bfloat162 lp = __floats2bfloat162_rn(o0 - __bfloat162float(hp.x),
                                              o1 - __bfloat162float(hp.y));
    *(__nv_bfloat162*)(hi + dofs) = hp;
    *(__nv_bfloat162*)(lo + dofs) = lp;
}

// ============================================================
// Tensor-core flash attention (bf16 3-term, FMA softmax).
// CTA: 128 queries x one (b,h). 8 warps x 16 rows. 64-key tiles.
// ============================================================
__global__ __launch_bounds__(256) void attn_mma(
    const __nv_bfloat16* __restrict__ Qh, const __nv_bfloat16* __restrict__ Ql,
    const __nv_bfloat16* __restrict__ Kh, const __nv_bfloat16* __restrict__ Kl,
    const __nv_bfloat16* __restrict__ Vh, const __nv_bfloat16* __restrict__ Vl,
    __nv_bfloat16* __restrict__ OHi, __nv_bfloat16* __restrict__ OLo)
{
    __shared__ __align__(16) char sm[32768];   // kh | kl | vh | vl (8KB each)
    const uint32_t sb = cvta_smem(sm);

    const int tid = threadIdx.x, warp = tid >> 5, lane = tid & 31;
    const int m0 = blockIdx.x * 128;
    const int h = blockIdx.y, b = blockIdx.z;
    const size_t hoff = (size_t)((b * NHEAD + h) * NSEQ);

    const int lrow16 = lane & 15, lchunk = lane >> 4;

    // ---- stage Q (hi then lo) through smem, build A-frags ----
    uint32_t qfh[4][4], qfl[4][4];
    {
        const __nv_bfloat16* Qsrc[2] = {Qh, Ql};
        const int r = warp * 16 + lrow16;
        const uint32_t rb = (uint32_t)(r * 128), msk = (uint32_t)((r & 7) << 4);
        for (int pass = 0; pass < 2; pass++) {
#pragma unroll
            for (int i = 0; i < 4; i++) {
                int id = tid + 256 * i;
                int row = id >> 3, ch = id & 7;
                *(uint4*)(sm + row * 128 + ((ch * 16) ^ ((row & 7) << 4))) =
                    *(const uint4*)(Qsrc[pass] + (hoff + m0 + row) * HDIM + ch * 8);
            }
            __syncthreads();
#pragma unroll
            for (int kc = 0; kc < 4; kc++) {
                uint32_t addr = sb + rb + (((uint32_t)(kc * 32 + lchunk * 16)) ^ msk);
                if (pass == 0) ldmx4(qfh[kc][0], qfh[kc][1], qfh[kc][2], qfh[kc][3], addr);
                else           ldmx4(qfl[kc][0], qfl[kc][1], qfl[kc][2], qfl[kc][3], addr);
            }
            __syncthreads();
        }
    }

    float o[8][4];
#pragma unroll
    for (int i = 0; i < 8; i++)
#pragma unroll
        for (int j = 0; j < 4; j++) o[i][j] = 0.f;
    float om0 = -1e30f, om1 = -1e30f, ol0 = 0.f, ol1 = 0.f;

    const __nv_bfloat16* srcs[4] = {Kh, Kl, Vh, Vl};

    for (int j0 = 0; j0 < NSEQ; j0 += 64) {
        // ---- load K/V hi+lo tiles (4 x 8KB) ----
#pragma unroll
        for (int i = 0; i < 8; i++) {
            int id = tid + 256 * i;
            int arr = id >> 9, row = (id >> 3) & 63, ch = id & 7;
            cp16(sb + arr * 8192 + (uint32_t)(row * 128 + ((ch * 16) ^ ((row & 7) << 4))),
                 srcs[arr] + (hoff + j0 + row) * HDIM + ch * 8);
        }
        cp_commit();
        asm volatile("cp.async.wait_group 0;");
        __syncthreads();

        // ---- S = qh*kh + ql*kh + qh*kl ----
        float s[8][4];
#pragma unroll
        for (int i = 0; i < 8; i++)
#pragma unroll
            for (int j = 0; j < 4; j++) s[i][j] = 0.f;
#pragma unroll
        for (int ng = 0; ng < 4; ng++) {
            const int r = ng * 16 + lrow16;
            const uint32_t rb = (uint32_t)(r * 128), msk = (uint32_t)((r & 7) << 4);
#pragma unroll
            for (int kc = 0; kc < 4; kc++) {
                const uint32_t co = (((uint32_t)(kc * 32 + lchunk * 16)) ^ msk);
                uint32_t k0, k1, k2, k3;
                ldmx4(k0, k1, k2, k3, sb + rb + co);               // khi
                mma16816(s[2*ng],   qfh[kc][0], qfh[kc][1], qfh[kc][2], qfh[kc][3], k0, k2);
                mma16816(s[2*ng+1], qfh[kc][0], qfh[kc][1], qfh[kc][2], qfh[kc][3], k1, k3);
                mma16816(s[2*ng],   qfl[kc][0], qfl[kc][1], qfl[kc][2], qfl[kc][3], k0, k2);
                mma16816(s[2*ng+1], qfl[kc][0], qfl[kc][1], qfl[kc][2], qfl[kc][3], k1, k3);
                ldmx4(k0, k1, k2, k3, sb + 8192 + rb + co);        // klo
                mma16816(s[2*ng],   qfh[kc][0], qfh[kc][1], qfh[kc][2], qfh[kc][3], k0, k2);
                mma16816(s[2*ng+1], qfh[kc][0], qfh[kc][1], qfh[kc][2], qfh[kc][3], k1, k3);
            }
        }

        // ---- online softmax (FMA exp) ----
        float tm0 = -1e30f, tm1 = -1e30f;
#pragma unroll
        for (int nb = 0; nb < 8; nb++) {
            tm0 = fmaxf(tm0, fmaxf(s[nb][0], s[nb][1]));
            tm1 = fmaxf(tm1, fmaxf(s[nb][2], s[nb][3]));
        }
        tm0 = fmaxf(tm0, __shfl_xor_sync(0xffffffffu, tm0, 1));
        tm0 = fmaxf(tm0, __shfl_xor_sync(0xffffffffu, tm0, 2));
        tm1 = fmaxf(tm1, __shfl_xor_sync(0xffffffffu, tm1, 1));
        tm1 = fmaxf(tm1, __shfl_xor_sync(0xffffffffu, tm1, 2));
        float mn0 = fmaxf(om0, tm0), mn1 = fmaxf(om1, tm1);
        float c0 = exp2f_fast((om0 - mn0) * L2E);
        float c1 = exp2f_fast((om1 - mn1) * L2E);
        om0 = mn0; om1 = mn1;
        const float nm0 = -mn0 * L2E, nm1 = -mn1 * L2E;

        float rs0 = 0.f, rs1 = 0.f;
        uint32_t pH01[8], pH23[8], pL01[8], pL23[8];
#pragma unroll
        for (int nb = 0; nb < 8; nb++) {
            float p0 = exp2f_fast(fmaf(s[nb][0], L2E, nm0));
            float p1 = exp2f_fast(fmaf(s[nb][1], L2E, nm0));
            float p2 = exp2f_fast(fmaf(s[nb][2], L2E, nm1));
            float p3 = exp2f_fast(fmaf(s[nb][3], L2E, nm1));
            rs0 += p0 + p1; rs1 += p2 + p3;
            __nv_bfloat162 h01 = __floats2bfloat162_rn(p0, p1);
            __nv_bfloat162 h23 = __floats2bfloat162_rn(p2, p3);
            __nv_bfloat162 l01 = __floats2bfloat162_rn(p0 - __bfloat162float(h01.x),
                                                       p1 - __bfloat162float(h01.y));
            __nv_bfloat162 l23 = __floats2bfloat162_rn(p2 - __bfloat162float(h23.x),
                                                       p3 - __bfloat162float(h23.y));
            pH01[nb] = *(uint32_t*)&h01; pH23[nb] = *(uint32_t*)&h23;
            pL01[nb] = *(uint32_t*)&l01; pL23[nb] = *(uint32_t*)&l23;
        }
        ol0 = fmaf(ol0, c0, rs0);
        ol1 = fmaf(ol1, c1, rs1);
#pragma unroll
        for (int db = 0; db < 8; db++) {
            o[db][0] *= c0; o[db][1] *= c0; o[db][2] *= c1; o[db][3] *= c1;
        }

        // ---- O += ph*vh + pl*vh + ph*vl  (V via ldmatrix.trans) ----
        const int t = lane >> 3;
        const int krow_base = (t & 1) * 8 + (lane & 7);
        const int ncol_base = (t >> 1) * 8;
#pragma unroll
        for (int kc = 0; kc < 4; kc++) {
            const uint32_t ah0 = pH01[2*kc], ah1 = pH23[2*kc];
            const uint32_t ah2 = pH01[2*kc+1], ah3 = pH23[2*kc+1];
            const uint32_t al0 = pL01[2*kc], al1 = pL23[2*kc];
            const uint32_t al2 = pL01[2*kc+1], al3 = pL23[2*kc+1];
            const int krow = kc * 16 + krow_base;
            const uint32_t roff = (uint32_t)(krow * 128);
            const uint32_t rmsk = (uint32_t)((krow & 7) << 4);
#pragma unroll
            for (int dg = 0; dg < 4; dg++) {
                const uint32_t aoff = roff + (((uint32_t)((dg * 16 + ncol_base) * 2)) ^ rmsk);
                uint32_t v0, v1, v2, v3;
                ldmx4t(v0, v1, v2, v3, sb + 16384 + aoff);          // vhi
                mma16816(o[2*dg],   ah0, ah1, ah2, ah3, v0, v1);
                mma16816(o[2*dg+1], ah0, ah1, ah2, ah3, v2, v3);
                mma16816(o[2*dg],   al0, al1, al2, al3, v0, v1);
                mma16816(o[2*dg+1], al0, al1, al2, al3, v2, v3);
                ldmx4t(v0, v1, v2, v3, sb + 24576 + aoff);          // vlo
                mma16816(o[2*dg],   ah0, ah1, ah2, ah3, v0, v1);
                mma16816(o[2*dg+1], ah0, ah1, ah2, ah3, v2, v3);
            }
        }
        __syncthreads();
    }

    // ---- FIX: row sum lives across the lane quad -> reduce before normalizing ----
    ol0 += __shfl_xor_sync(0xffffffffu, ol0, 1);
    ol0 += __shfl_xor_sync(0xffffffffu, ol0, 2);
    ol1 += __shfl_xor_sync(0xffffffffu, ol1, 1);
    ol1 += __shfl_xor_sync(0xffffffffu, ol1, 2);

    // ---- epilogue: normalize, split to bf16 hi/lo, store [B,N,C] ----
    const float i0 = 1.f / ol0, i1 = 1.f / ol1;
    const int r0 = m0 + warp * 16 + (lane >> 2), r1 = r0 + 8;
    const int cb = h * HDIM + (lane & 3) * 2;
#pragma unroll
    for (int db = 0; db < 8; db++) {
        const int c = cb + db * 8;
        float a0 = o[db][0] * i0, a1 = o[db][1] * i0;
        float a2 = o[db][2] * i1, a3 = o[db][3] * i1;
        __nv_bfloat162 h01 = __floats2bfloat162_rn(a0, a1);
        __nv_bfloat162 l01 = __floats2bfloat162_rn(a0 - __bfloat162float(h01.x),
                                                   a1 - __bfloat162float(h01.y));
        __nv_bfloat162 h23 = __floats2bfloat162_rn(a2, a3);
        __nv_bfloat162 l23 = __floats2bfloat162_rn(a2 - __bfloat162float(h23.x),
                                                   a3 - __bfloat162float(h23.y));
        *(__nv_bfloat162*)(OHi + (size_t)(b * NSEQ + r0) * DIMC + c) = h01;
        *(__nv_bfloat162*)(OLo + (size_t)(b * NSEQ + r0) * DIMC + c) = l01;
        *(__nv_bfloat162*)(OHi + (size_t)(b * NSEQ + r1) * DIMC + c) = h23;
        *(__nv_bfloat162*)(OLo + (size_t)(b * NSEQ + r1) * DIMC + c) = l23;
    }
}

// ============================================================
extern "C" void kernel_launch(void* const* d_in, const int* in_sizes, int n_in,
                              void* d_out, int out_size)
{
    const float* x      = (const float*)d_in[0];
    const float* pos    = (const float*)d_in[1];
    const float* qkv_w  = (const float*)d_in[2];
    const float* qnw    = (const float*)d_in[3];
    const float* knw    = (const float*)d_in[4];
    const float* proj_w = (const float*)d_in[5];
    const float* proj_b = (const float*)d_in[6];
    float* out = (float*)d_out;

    float *qkv;
    __nv_bfloat16 *xhi, *xlo, *whi, *wlo, *phi, *plo, *ahi, *alo;
    __nv_bfloat16 *qhi, *qlo, *khi, *klo, *vhi, *vlo;
    cudaGetSymbolAddress((void**)&qkv, g_qkv);
    cudaGetSymbolAddress((void**)&xhi, g_xhi);  cudaGetSymbolAddress((void**)&xlo, g_xlo);
    cudaGetSymbolAddress((void**)&whi, g_whi);  cudaGetSymbolAddress((void**)&wlo, g_wlo);
    cudaGetSymbolAddress((void**)&phi, g_phi);  cudaGetSymbolAddress((void**)&plo, g_plo);
    cudaGetSymbolAddress((void**)&ahi, g_ahi);  cudaGetSymbolAddress((void**)&alo, g_alo);
    cudaGetSymbolAddress((void**)&qhi, g_qhi);  cudaGetSymbolAddress((void**)&qlo, g_qlo);
    cudaGetSymbolAddress((void**)&khi, g_khi);  cudaGetSymbolAddress((void**)&klo, g_klo);
    cudaGetSymbolAddress((void**)&vhi, g_vhi);  cudaGetSymbolAddress((void**)&vlo, g_vlo);

    cudaFuncSetAttribute(mma_gemm<0>, cudaFuncAttributeMaxDynamicSharedMemorySize, SMEM_TOT);
    cudaFuncSetAttribute(mma_gemm<1>, cudaFuncAttributeMaxDynamicSharedMemorySize, SMEM_TOT);

    // 0) bf16 hi/lo splits of inputs
    split_kernel<<<(ROWS * DIMC / 4 + 255) / 256, 256>>>(x, xhi, xlo, ROWS * DIMC / 4);
    split_kernel<<<(QKV_F * DIMC / 4 + 255) / 256, 256>>>(qkv_w, whi, wlo, QKV_F * DIMC / 4);
    split_kernel<<<(DIMC * DIMC / 4 + 255) / 256, 256>>>(proj_w, phi, plo, DIMC * DIMC / 4);

    // 1) QKV projection (tensor cores, 3-term)
    mma_gemm<0><<<dim3(QKV_F / 128, ROWS / 128), 256, SMEM_TOT>>>(
        xhi, xhi, xlo, whi, wlo, whi, qkv, nullptr, QKV_F);

    // 2) RMSNorm + rotary (q,k) and split (v) -> bf16 hi/lo [B,H,N,D]
    rms_rot_kernel<<<(3 * BQ * NHEAD * NSEQ) / 8, 256>>>(
        qkv, pos, qnw, knw, qhi, qlo, khi, klo, vhi, vlo);

    // 3) Tensor-core flash attention -> bf16 hi/lo [B,N,C]
    attn_mma<<<dim3(NSEQ / 128, NHEAD, BQ), 256>>>(
        qhi, qlo, khi, klo, vhi, vlo, ahi, alo);

    // 4) proj (tensor cores, 3-term) + bias
    mma_gemm<1><<<dim3(DIMC / 128, ROWS / 128), 256, SMEM_TOT>>>(
        ahi, ahi, alo, phi, plo, phi, out, proj_b, DIMC);
}

// round 10
// speedup vs baseline: 4.0800x; 1.0040x over previous
#include <cuda_runtime.h>
#include <cuda_bf16.h>
#include <math.h>
#include <stdint.h>

#define DIMC  1024
#define NHEAD 16
#define HDIM  64
#define BQ    2
#define NSEQ  2048
#define ROWS  (BQ*NSEQ)      // 4096
#define QKV_F (3*DIMC)       // 3072
#define L2E   1.4426950408889634f

// ---- scratch (no allocations allowed) ----
__device__ float g_qkv [ROWS * QKV_F];
__device__ __nv_bfloat16 g_xhi[ROWS * DIMC];
__device__ __nv_bfloat16 g_xlo[ROWS * DIMC];
__device__ __nv_bfloat16 g_whi[QKV_F * DIMC];
__device__ __nv_bfloat16 g_wlo[QKV_F * DIMC];
__device__ __nv_bfloat16 g_phi[DIMC * DIMC];
__device__ __nv_bfloat16 g_plo[DIMC * DIMC];
__device__ __nv_bfloat16 g_ahi[ROWS * DIMC];
__device__ __nv_bfloat16 g_alo[ROWS * DIMC];
// [B,H,N,D] bf16 hi/lo operands for attention
__device__ __nv_bfloat16 g_qhi[ROWS * DIMC];
__device__ __nv_bfloat16 g_qlo[ROWS * DIMC];
__device__ __nv_bfloat16 g_khi[ROWS * DIMC];
__device__ __nv_bfloat16 g_klo[ROWS * DIMC];
__device__ __nv_bfloat16 g_vhi[ROWS * DIMC];
__device__ __nv_bfloat16 g_vlo[ROWS * DIMC];

__device__ __forceinline__ uint32_t cvta_smem(const void* p) {
    uint32_t a;
    asm("{ .reg .u64 t; cvta.to.shared.u64 t, %1; cvt.u32.u64 %0, t; }" : "=r"(a) : "l"(p));
    return a;
}
__device__ __forceinline__ void cp16(uint32_t dst, const void* src) {
    asm volatile("cp.async.ca.shared.global [%0], [%1], 16;" :: "r"(dst), "l"(src));
}
__device__ __forceinline__ void cp_commit() {
    asm volatile("cp.async.commit_group;");
}
__device__ __forceinline__ void ldmx4(uint32_t& r0, uint32_t& r1, uint32_t& r2, uint32_t& r3,
                                      uint32_t addr) {
    asm volatile("ldmatrix.sync.aligned.m8n8.x4.shared.b16 {%0,%1,%2,%3}, [%4];"
                 : "=r"(r0), "=r"(r1), "=r"(r2), "=r"(r3) : "r"(addr));
}
__device__ __forceinline__ void ldmx4t(uint32_t& r0, uint32_t& r1, uint32_t& r2, uint32_t& r3,
                                       uint32_t addr) {
    asm volatile("ldmatrix.sync.aligned.m8n8.x4.trans.shared.b16 {%0,%1,%2,%3}, [%4];"
                 : "=r"(r0), "=r"(r1), "=r"(r2), "=r"(r3) : "r"(addr));
}
__device__ __forceinline__ void mma16816(float* d,
                                         uint32_t a0, uint32_t a1, uint32_t a2, uint32_t a3,
                                         uint32_t b0, uint32_t b1) {
    asm volatile(
        "mma.sync.aligned.m16n8k16.row.col.f32.bf16.bf16.f32 "
        "{%0,%1,%2,%3}, {%4,%5,%6,%7}, {%8,%9}, {%0,%1,%2,%3};"
        : "+f"(d[0]), "+f"(d[1]), "+f"(d[2]), "+f"(d[3])
        : "r"(a0), "r"(a1), "r"(a2), "r"(a3), "r"(b0), "r"(b1));
}
// exp2 on the FMA pipe: magic-round + deg-5 poly + exponent add
__device__ __forceinline__ float exp2f_fast(float y) {
    y = fmaxf(y, -120.f);
    float t  = y + 12582912.f;           // 1.5*2^23
    float fl = t - 12582912.f;
    float fr = y - fl;                   // [-0.5, 0.5]
    float p = 0.0013333558f;
    p = fmaf(p, fr, 0.0096181291f);
    p = fmaf(p, fr, 0.0555041087f);
    p = fmaf(p, fr, 0.2402265069f);
    p = fmaf(p, fr, 0.6931471806f);
    p = fmaf(p, fr, 1.0f);
    int e = __float_as_int(t) << 23;
    return __int_as_float(__float_as_int(p) + e);
}

// ============================================================
// mma.sync bf16 GEMM (NT), 3-term compensated, 3-stage cp.async pipeline,
// register-level fragment ping-pong in the inner loop.
// ============================================================
#define KSEG 1024
#define NCHT 48
#define OPND 16384
#define STAGEB (2*OPND)
#define SMEM_TOT (3*STAGEB)

template<int TAG>
__global__ __launch_bounds__(256, 2) void mma_gemm(
    const __nv_bfloat16* __restrict__ A0, const __nv_bfloat16* __restrict__ A1,
    const __nv_bfloat16* __restrict__ A2,
    const __nv_bfloat16* __restrict__ B0, const __nv_bfloat16* __restrict__ B1,
    const __nv_bfloat16* __restrict__ B2,
    float* __restrict__ C, const float* __restrict__ bias, int ldC)
{
    extern __shared__ char smem[];
    const uint32_t sbase = cvta_smem(smem);

    const int tid  = threadIdx.x;
    const int warp = tid >> 5;
    const int lane = tid & 31;
    const int wm   = warp >> 2;
    const int wn   = warp & 3;
    const int m0 = blockIdx.y * 128;
    const int n0 = blockIdx.x * 128;

    const __nv_bfloat16* Asegs[3] = {A0, A1, A2};
    const __nv_bfloat16* Bsegs[3] = {B0, B1, B2};

    const int lrow = tid >> 3;
    const int lch  = tid & 7;

    auto issue_tile = [&](int kt, int stg) {
        const int seg = kt >> 4;
        const int kc  = (kt & 15) * 64;
        const __nv_bfloat16* Ap = Asegs[seg];
        const __nv_bfloat16* Bp = Bsegs[seg];
        const uint32_t base = sbase + stg * STAGEB;
#pragma unroll
        for (int i = 0; i < 4; i++) {
            int row = lrow + 32 * i;
            uint32_t soff = (uint32_t)(row * 128 + ((lch * 16) ^ ((row & 7) << 4)));
            cp16(base + soff,        Ap + (size_t)(m0 + row) * KSEG + kc + lch * 8);
            cp16(base + OPND + soff, Bp + (size_t)(n0 + row) * KSEG + kc + lch * 8);
        }
        cp_commit();
    };

    float acc[4][4][4];
#pragma unroll
    for (int i = 0; i < 4; i++)
#pragma unroll
        for (int j = 0; j < 4; j++)
#pragma unroll
            for (int v = 0; v < 4; v++) acc[i][j][v] = 0.f;

    const int lrow16 = lane & 15;
    const int lchunk = lane >> 4;
    uint32_t aRow[4], aMask[4];
#pragma unroll
    for (int fi = 0; fi < 4; fi++) {
        int r = wm * 64 + fi * 16 + lrow16;
        aRow[fi]  = (uint32_t)(r * 128);
        aMask[fi] = (uint32_t)((r & 7) << 4);
    }
    uint32_t bRow[2], bMask[2];
#pragma unroll
    for (int nj = 0; nj < 2; nj++) {
        int r = wn * 32 + nj * 16 + lrow16;
        bRow[nj]  = (uint32_t)(r * 128 + OPND);
        bMask[nj] = (uint32_t)((r & 7) << 4);
    }

    auto load_frags = [&](uint32_t (&af)[4][4], uint32_t (&bf)[2][4],
                          uint32_t base, int ks) {
        const uint32_t kb = (uint32_t)(ks * 32 + lchunk * 16);
#pragma unroll
        for (int fi = 0; fi < 4; fi++)
            ldmx4(af[fi][0], af[fi][1], af[fi][2], af[fi][3],
                  base + aRow[fi] + (kb ^ aMask[fi]));
#pragma unroll
        for (int nj = 0; nj < 2; nj++)
            ldmx4(bf[nj][0], bf[nj][1], bf[nj][2], bf[nj][3],
                  base + bRow[nj] + (kb ^ bMask[nj]));
    };

    issue_tile(0, 0);
    issue_tile(1, 1);

    for (int kt = 0; kt < NCHT; kt++) {
        const int stg = kt - (kt / 3) * 3;
        if (kt + 1 < NCHT) asm volatile("cp.async.wait_group 1;");
        else               asm volatile("cp.async.wait_group 0;");
        __syncthreads();
        if (kt + 2 < NCHT) issue_tile(kt + 2, (kt + 2) - ((kt + 2) / 3) * 3);

        const uint32_t base = sbase + stg * STAGEB;
        uint32_t afr[2][4][4], bfr[2][2][4];
        load_frags(afr[0], bfr[0], base, 0);
#pragma unroll
        for (int ks = 0; ks < 4; ks++) {
            const int cur = ks & 1;
            if (ks < 3) load_frags(afr[cur ^ 1], bfr[cur ^ 1], base, ks + 1);
#pragma unroll
            for (int fi = 0; fi < 4; fi++) {
#pragma unroll
                for (int nj = 0; nj < 2; nj++) {
                    mma16816(acc[fi][2*nj],   afr[cur][fi][0], afr[cur][fi][1],
                             afr[cur][fi][2], afr[cur][fi][3],
                             bfr[cur][nj][0], bfr[cur][nj][2]);
                    mma16816(acc[fi][2*nj+1], afr[cur][fi][0], afr[cur][fi][1],
                             afr[cur][fi][2], afr[cur][fi][3],
                             bfr[cur][nj][1], bfr[cur][nj][3]);
                }
            }
        }
    }

    const int mrow = m0 + wm * 64 + (lane >> 2);
    const int ncol = n0 + wn * 32 + (lane & 3) * 2;
#pragma unroll
    for (int fi = 0; fi < 4; fi++) {
#pragma unroll
        for (int nb = 0; nb < 4; nb++) {
            int r = mrow + fi * 16;
            int c = ncol + nb * 8;
            float b0 = 0.f, b1 = 0.f;
            if (bias) { b0 = bias[c]; b1 = bias[c + 1]; }
            *(float2*)&C[(size_t)r * ldC + c] =
                make_float2(acc[fi][nb][0] + b0, acc[fi][nb][1] + b1);
            *(float2*)&C[(size_t)(r + 8) * ldC + c] =
                make_float2(acc[fi][nb][2] + b0, acc[fi][nb][3] + b1);
        }
    }
}

// ============================================================
// fp32 -> bf16 hi/lo split
// ============================================================
__global__ __launch_bounds__(256) void split_kernel(
    const float* __restrict__ in, __nv_bfloat16* __restrict__ hi,
    __nv_bfloat16* __restrict__ lo, int n4)
{
    int i = blockIdx.x * blockDim.x + threadIdx.x;
    if (i >= n4) return;
    float4 v = ((const float4*)in)[i];
    __nv_bfloat16 h[4], l[4];
    float x[4] = {v.x, v.y, v.z, v.w};
#pragma unroll
    for (int j = 0; j < 4; j++) {
        h[j] = __float2bfloat16_rn(x[j]);
        l[j] = __float2bfloat16_rn(x[j] - __bfloat162float(h[j]));
    }
    ((uint2*)hi)[i] = *(const uint2*)h;
    ((uint2*)lo)[i] = *(const uint2*)l;
}

// ============================================================
// RMSNorm + rotary for q,k and raw split for v.
// ============================================================
__global__ __launch_bounds__(256) void rms_rot_kernel(
    const float* __restrict__ qkv, const float* __restrict__ pos,
    const float* __restrict__ qw, const float* __restrict__ kw,
    __nv_bfloat16* __restrict__ qhi, __nv_bfloat16* __restrict__ qlo,
    __nv_bfloat16* __restrict__ khi, __nv_bfloat16* __restrict__ klo,
    __nv_bfloat16* __restrict__ vhi, __nv_bfloat16* __restrict__ vlo)
{
    int wgi  = blockIdx.x * (blockDim.x >> 5) + (threadIdx.x >> 5);
    int lane = threadIdx.x & 31;
    int n   =  wgi        & (NSEQ - 1);
    int h   = (wgi >> 11) & (NHEAD - 1);
    int b   = (wgi >> 15) & 1;
    int sel =  wgi >> 16;                     // 0=q, 1=k, 2=v

    const float* src = qkv + (size_t)(b * NSEQ + n) * QKV_F + sel * DIMC + h * HDIM + 2 * lane;
    float2 v = *(const float2*)src;

    float o0, o1;
    if (sel < 2) {
        float ss = v.x * v.x + v.y * v.y;
#pragma unroll
        for (int o = 16; o; o >>= 1) ss += __shfl_xor_sync(0xffffffffu, ss, o);
        float r = rsqrtf(ss * (1.f / HDIM) + 1e-6f);
        const float* w = sel ? kw : qw;
        float xr = v.x * r * w[2 * lane];
        float xi = v.y * r * w[2 * lane + 1];
        float ang = pos[n * (HDIM / 2) + lane];
        float sn, cs;
        __sincosf(ang, &sn, &cs);
        o0 = xr * cs - xi * sn;
        o1 = xr * sn + xi * cs;
        if (!sel) { o0 *= 0.125f; o1 *= 0.125f; }
    } else {
        o0 = v.x; o1 = v.y;
    }

    __nv_bfloat16* hi = (sel == 0) ? qhi : (sel == 1) ? khi : vhi;
    __nv_bfloat16* lo = (sel == 0) ? qlo : (sel == 1) ? klo : vlo;
    size_t dofs = (size_t)((b * NHEAD + h) * NSEQ + n) * HDIM + 2 * lane;
    __nv_bfloat162 hp = __floats2bfloat162_rn(o0, o1);
    __nv_bfloat162 lp = __floats2bfloat162_rn(o0 - __bfloat162float(hp.x),
                                              o1 - __bfloat162float(hp.y));
    *(__nv_bfloat162*)(hi + dofs) = hp;
    *(__nv_bfloat162*)(lo + dofs) = lp;
}

// ============================================================
// Tensor-core flash attention (bf16 3-term, FMA softmax),
// double-buffered K/V smem (2 x 32KB stages, dynamic).
// ============================================================
#define ATTN_STAGE 32768
#define ATTN_SMEM  (2*ATTN_STAGE)

__global__ __launch_bounds__(256) void attn_mma(
    const __nv_bfloat16* __restrict__ Qh, const __nv_bfloat16* __restrict__ Ql,
    const __nv_bfloat16* __restrict__ Kh, const __nv_bfloat16* __restrict__ Kl,
    const __nv_bfloat16* __restrict__ Vh, const __nv_bfloat16* __restrict__ Vl,
    __nv_bfloat16* __restrict__ OHi, __nv_bfloat16* __restrict__ OLo)
{
    extern __shared__ __align__(16) char sm[];
    const uint32_t sb = cvta_smem(sm);

    const int tid = threadIdx.x, warp = tid >> 5, lane = tid & 31;
    const int m0 = blockIdx.x * 128;
    const int h = blockIdx.y, b = blockIdx.z;
    const size_t hoff = (size_t)((b * NHEAD + h) * NSEQ);

    const int lrow16 = lane & 15, lchunk = lane >> 4;

    // ---- stage Q (hi then lo) through smem, build A-frags ----
    uint32_t qfh[4][4], qfl[4][4];
    {
        const __nv_bfloat16* Qsrc[2] = {Qh, Ql};
        const int r = warp * 16 + lrow16;
        const uint32_t rb = (uint32_t)(r * 128), msk = (uint32_t)((r & 7) << 4);
        for (int pass = 0; pass < 2; pass++) {
#pragma unroll
            for (int i = 0; i < 4; i++) {
                int id = tid + 256 * i;
                int row = id >> 3, ch = id & 7;
                *(uint4*)(sm + row * 128 + ((ch * 16) ^ ((row & 7) << 4))) =
                    *(const uint4*)(Qsrc[pass] + (hoff + m0 + row) * HDIM + ch * 8);
            }
            __syncthreads();
#pragma unroll
            for (int kc = 0; kc < 4; kc++) {
                uint32_t addr = sb + rb + (((uint32_t)(kc * 32 + lchunk * 16)) ^ msk);
                if (pass == 0) ldmx4(qfh[kc][0], qfh[kc][1], qfh[kc][2], qfh[kc][3], addr);
                else           ldmx4(qfl[kc][0], qfl[kc][1], qfl[kc][2], qfl[kc][3], addr);
            }
            __syncthreads();
        }
    }

    float o[8][4];
#pragma unroll
    for (int i = 0; i < 8; i++)
#pragma unroll
        for (int j = 0; j < 4; j++) o[i][j] = 0.f;
    float om0 = -1e30f, om1 = -1e30f, ol0 = 0.f, ol1 = 0.f;

    const __nv_bfloat16* srcs[4] = {Kh, Kl, Vh, Vl};

    auto issue_kv = [&](int j0, int stg) {
#pragma unroll
        for (int i = 0; i < 8; i++) {
            int id = tid + 256 * i;
            int arr = id >> 9, row = (id >> 3) & 63, ch = id & 7;
            cp16(sb + stg * ATTN_STAGE + arr * 8192 +
                     (uint32_t)(row * 128 + ((ch * 16) ^ ((row & 7) << 4))),
                 srcs[arr] + (hoff + j0 + row) * HDIM + ch * 8);
        }
        cp_commit();
    };

    issue_kv(0, 0);

    const int NT = NSEQ / 64;
    for (int t = 0; t < NT; t++) {
        const int buf = t & 1;
        if (t + 1 < NT) {
            issue_kv((t + 1) * 64, buf ^ 1);
            asm volatile("cp.async.wait_group 1;");
        } else {
            asm volatile("cp.async.wait_group 0;");
        }
        __syncthreads();
        const uint32_t stb = sb + buf * ATTN_STAGE;

        // ---- S = qh*kh + ql*kh + qh*kl ----
        float s[8][4];
#pragma unroll
        for (int i = 0; i < 8; i++)
#pragma unroll
            for (int j = 0; j < 4; j++) s[i][j] = 0.f;
#pragma unroll
        for (int ng = 0; ng < 4; ng++) {
            const int r = ng * 16 + lrow16;
            const uint32_t rb = (uint32_t)(r * 128), msk = (uint32_t)((r & 7) << 4);
#pragma unroll
            for (int kc = 0; kc < 4; kc++) {
                const uint32_t co = (((uint32_t)(kc * 32 + lchunk * 16)) ^ msk);
                uint32_t k0, k1, k2, k3;
                ldmx4(k0, k1, k2, k3, stb + rb + co);               // khi
                mma16816(s[2*ng],   qfh[kc][0], qfh[kc][1], qfh[kc][2], qfh[kc][3], k0, k2);
                mma16816(s[2*ng+1], qfh[kc][0], qfh[kc][1], qfh[kc][2], qfh[kc][3], k1, k3);
                mma16816(s[2*ng],   qfl[kc][0], qfl[kc][1], qfl[kc][2], qfl[kc][3], k0, k2);
                mma16816(s[2*ng+1], qfl[kc][0], qfl[kc][1], qfl[kc][2], qfl[kc][3], k1, k3);
                ldmx4(k0, k1, k2, k3, stb + 8192 + rb + co);        // klo
                mma16816(s[2*ng],   qfh[kc][0], qfh[kc][1], qfh[kc][2], qfh[kc][3], k0, k2);
                mma16816(s[2*ng+1], qfh[kc][0], qfh[kc][1], qfh[kc][2], qfh[kc][3], k1, k3);
            }
        }

        // ---- online softmax (FMA exp) ----
        float tm0 = -1e30f, tm1 = -1e30f;
#pragma unroll
        for (int nb = 0; nb < 8; nb++) {
            tm0 = fmaxf(tm0, fmaxf(s[nb][0], s[nb][1]));
            tm1 = fmaxf(tm1, fmaxf(s[nb][2], s[nb][3]));
        }
        tm0 = fmaxf(tm0, __shfl_xor_sync(0xffffffffu, tm0, 1));
        tm0 = fmaxf(tm0, __shfl_xor_sync(0xffffffffu, tm0, 2));
        tm1 = fmaxf(tm1, __shfl_xor_sync(0xffffffffu, tm1, 1));
        tm1 = fmaxf(tm1, __shfl_xor_sync(0xffffffffu, tm1, 2));
        float mn0 = fmaxf(om0, tm0), mn1 = fmaxf(om1, tm1);
        float c0 = exp2f_fast((om0 - mn0) * L2E);
        float c1 = exp2f_fast((om1 - mn1) * L2E);
        om0 = mn0; om1 = mn1;
        const float nm0 = -mn0 * L2E, nm1 = -mn1 * L2E;

        float rs0 = 0.f, rs1 = 0.f;
        uint32_t pH01[8], pH23[8], pL01[8], pL23[8];
#pragma unroll
        for (int nb = 0; nb < 8; nb++) {
            float p0 = exp2f_fast(fmaf(s[nb][0], L2E, nm0));
            float p1 = exp2f_fast(fmaf(s[nb][1], L2E, nm0));
            float p2 = exp2f_fast(fmaf(s[nb][2], L2E, nm1));
            float p3 = exp2f_fast(fmaf(s[nb][3], L2E, nm1));
            rs0 += p0 + p1; rs1 += p2 + p3;
            __nv_bfloat162 h01 = __floats2bfloat162_rn(p0, p1);
            __nv_bfloat162 h23 = __floats2bfloat162_rn(p2, p3);
            __nv_bfloat162 l01 = __floats2bfloat162_rn(p0 - __bfloat162float(h01.x),
                                                       p1 - __bfloat162float(h01.y));
            __nv_bfloat162 l23 = __floats2bfloat162_rn(p2 - __bfloat162float(h23.x),
                                                       p3 - __bfloat162float(h23.y));
            pH01[nb] = *(uint32_t*)&h01; pH23[nb] = *(uint32_t*)&h23;
            pL01[nb] = *(uint32_t*)&l01; pL23[nb] = *(uint32_t*)&l23;
        }
        ol0 = fmaf(ol0, c0, rs0);
        ol1 = fmaf(ol1, c1, rs1);
#pragma unroll
        for (int db = 0; db < 8; db++) {
            o[db][0] *= c0; o[db][1] *= c0; o[db][2] *= c1; o[db][3] *= c1;
        }

        // ---- O += ph*vh + pl*vh + ph*vl  (V via ldmatrix.trans) ----
        const int tq = lane >> 3;
        const int krow_base = (tq & 1) * 8 + (lane & 7);
        const int ncol_base = (tq >> 1) * 8;
#pragma unroll
        for (int kc = 0; kc < 4; kc++) {
            const uint32_t ah0 = pH01[2*kc], ah1 = pH23[2*kc];
            const uint32_t ah2 = pH01[2*kc+1], ah3 = pH23[2*kc+1];
            const uint32_t al0 = pL01[2*kc], al1 = pL23[2*kc];
            const uint32_t al2 = pL01[2*kc+1], al3 = pL23[2*kc+1];
            const int krow = kc * 16 + krow_base;
            const uint32_t roff = (uint32_t)(krow * 128);
            const uint32_t rmsk = (uint32_t)((krow & 7) << 4);
#pragma unroll
            for (int dg = 0; dg < 4; dg++) {
                const uint32_t aoff = roff + (((uint32_t)((dg * 16 + ncol_base) * 2)) ^ rmsk);
                uint32_t v0, v1, v2, v3;
                ldmx4t(v0, v1, v2, v3, stb + 16384 + aoff);          // vhi
                mma16816(o[2*dg],   ah0, ah1, ah2, ah3, v0, v1);
                mma16816(o[2*dg+1], ah0, ah1, ah2, ah3, v2, v3);
                mma16816(o[2*dg],   al0, al1, al2, al3, v0, v1);
                mma16816(o[2*dg+1], al0, al1, al2, al3, v2, v3);
                ldmx4t(v0, v1, v2, v3, stb + 24576 + aoff);          // vlo
                mma16816(o[2*dg],   ah0, ah1, ah2, ah3, v0, v1);
                mma16816(o[2*dg+1], ah0, ah1, ah2, ah3, v2, v3);
            }
        }
        __syncthreads();
    }

    // ---- row sum lives across the lane quad -> reduce before normalizing ----
    ol0 += __shfl_xor_sync(0xffffffffu, ol0, 1);
    ol0 += __shfl_xor_sync(0xffffffffu, ol0, 2);
    ol1 += __shfl_xor_sync(0xffffffffu, ol1, 1);
    ol1 += __shfl_xor_sync(0xffffffffu, ol1, 2);

    // ---- epilogue: normalize, split to bf16 hi/lo, store [B,N,C] ----
    const float i0 = 1.f / ol0, i1 = 1.f / ol1;
    const int r0 = m0 + warp * 16 + (lane >> 2), r1 = r0 + 8;
    const int cb = h * HDIM + (lane & 3) * 2;
#pragma unroll
    for (int db = 0; db < 8; db++) {
        const int c = cb + db * 8;
        float a0 = o[db][0] * i0, a1 = o[db][1] * i0;
        float a2 = o[db][2] * i1, a3 = o[db][3] * i1;
        __nv_bfloat162 h01 = __floats2bfloat162_rn(a0, a1);
        __nv_bfloat162 l01 = __floats2bfloat162_rn(a0 - __bfloat162float(h01.x),
                                                   a1 - __bfloat162float(h01.y));
        __nv_bfloat162 h23 = __floats2bfloat162_rn(a2, a3);
        __nv_bfloat162 l23 = __floats2bfloat162_rn(a2 - __bfloat162float(h23.x),
                                                   a3 - __bfloat162float(h23.y));
        *(__nv_bfloat162*)(OHi + (size_t)(b * NSEQ + r0) * DIMC + c) = h01;
        *(__nv_bfloat162*)(OLo + (size_t)(b * NSEQ + r0) * DIMC + c) = l01;
        *(__nv_bfloat162*)(OHi + (size_t)(b * NSEQ + r1) * DIMC + c) = h23;
        *(__nv_bfloat162*)(OLo + (size_t)(b * NSEQ + r1) * DIMC + c) = l23;
    }
}

// ============================================================
extern "C" void kernel_launch(void* const* d_in, const int* in_sizes, int n_in,
                              void* d_out, int out_size)
{
    const float* x      = (const float*)d_in[0];
    const float* pos    = (const float*)d_in[1];
    const float* qkv_w  = (const float*)d_in[2];
    const float* qnw    = (const float*)d_in[3];
    const float* knw    = (const float*)d_in[4];
    const float* proj_w = (const float*)d_in[5];
    const float* proj_b = (const float*)d_in[6];
    float* out = (float*)d_out;

    float *qkv;
    __nv_bfloat16 *xhi, *xlo, *whi, *wlo, *phi, *plo, *ahi, *alo;
    __nv_bfloat16 *qhi, *qlo, *khi, *klo, *vhi, *vlo;
    cudaGetSymbolAddress((void**)&qkv, g_qkv);
    cudaGetSymbolAddress((void**)&xhi, g_xhi);  cudaGetSymbolAddress((void**)&xlo, g_xlo);
    cudaGetSymbolAddress((void**)&whi, g_whi);  cudaGetSymbolAddress((void**)&wlo, g_wlo);
    cudaGetSymbolAddress((void**)&phi, g_phi);  cudaGetSymbolAddress((void**)&plo, g_plo);
    cudaGetSymbolAddress((void**)&ahi, g_ahi);  cudaGetSymbolAddress((void**)&alo, g_alo);
    cudaGetSymbolAddress((void**)&qhi, g_qhi);  cudaGetSymbolAddress((void**)&qlo, g_qlo);
    cudaGetSymbolAddress((void**)&khi, g_khi);  cudaGetSymbolAddress((void**)&klo, g_klo);
    cudaGetSymbolAddress((void**)&vhi, g_vhi);  cudaGetSymbolAddress((void**)&vlo, g_vlo);

    cudaFuncSetAttribute(mma_gemm<0>, cudaFuncAttributeMaxDynamicSharedMemorySize, SMEM_TOT);
    cudaFuncSetAttribute(mma_gemm<1>, cudaFuncAttributeMaxDynamicSharedMemorySize, SMEM_TOT);
    cudaFuncSetAttribute(attn_mma, cudaFuncAttributeMaxDynamicSharedMemorySize, ATTN_SMEM);

    // 0) bf16 hi/lo splits of inputs
    split_kernel<<<(ROWS * DIMC / 4 + 255) / 256, 256>>>(x, xhi, xlo, ROWS * DIMC / 4);
    split_kernel<<<(QKV_F * DIMC / 4 + 255) / 256, 256>>>(qkv_w, whi, wlo, QKV_F * DIMC / 4);
    split_kernel<<<(DIMC * DIMC / 4 + 255) / 256, 256>>>(proj_w, phi, plo, DIMC * DIMC / 4);

    // 1) QKV projection (tensor cores, 3-term)
    mma_gemm<0><<<dim3(QKV_F / 128, ROWS / 128), 256, SMEM_TOT>>>(
        xhi, xhi, xlo, whi, wlo, whi, qkv, nullptr, QKV_F);

    // 2) RMSNorm + rotary (q,k) and split (v) -> bf16 hi/lo [B,H,N,D]
    rms_rot_kernel<<<(3 * BQ * NHEAD * NSEQ) / 8, 256>>>(
        qkv, pos, qnw, knw, qhi, qlo, khi, klo, vhi, vlo);

    // 3) Tensor-core flash attention -> bf16 hi/lo [B,N,C]
    attn_mma<<<dim3(NSEQ / 128, NHEAD, BQ), 256, ATTN_SMEM>>>(
        qhi, qlo, khi, klo, vhi, vlo, ahi, alo);

    // 4) proj (tensor cores, 3-term) + bias
    mma_gemm<1><<<dim3(DIMC / 128, ROWS / 128), 256, SMEM_TOT>>>(
        ahi, ahi, alo, phi, plo, phi, out, proj_b, DIMC);
}

// round 11
// speedup vs baseline: 4.9700x; 1.2181x over previous
#include <cuda_runtime.h>
#include <cuda_bf16.h>
#include <cuda_fp16.h>
#include <math.h>
#include <stdint.h>

#define DIMC  1024
#define NHEAD 16
#define HDIM  64
#define BQ    2
#define NSEQ  2048
#define ROWS  (BQ*NSEQ)      // 4096
#define QKV_F (3*DIMC)       // 3072
#define L2E   1.4426950408889634f

// ---- scratch (no allocations allowed) ----
__device__ float g_qkv [ROWS * QKV_F];
__device__ __half g_xhi[ROWS * DIMC];
__device__ __half g_xlo[ROWS * DIMC];
__device__ __half g_whi[QKV_F * DIMC];
__device__ __half g_phi[DIMC * DIMC];
__device__ __half g_ahi[ROWS * DIMC];
__device__ __half g_alo[ROWS * DIMC];
// [B,H,N,D] bf16 hi/lo operands for attention (3-term path, unchanged)
__device__ __nv_bfloat16 g_qhi[ROWS * DIMC];
__device__ __nv_bfloat16 g_qlo[ROWS * DIMC];
__device__ __nv_bfloat16 g_khi[ROWS * DIMC];
__device__ __nv_bfloat16 g_klo[ROWS * DIMC];
__device__ __nv_bfloat16 g_vhi[ROWS * DIMC];
__device__ __nv_bfloat16 g_vlo[ROWS * DIMC];

__device__ __forceinline__ uint32_t cvta_smem(const void* p) {
    uint32_t a;
    asm("{ .reg .u64 t; cvta.to.shared.u64 t, %1; cvt.u32.u64 %0, t; }" : "=r"(a) : "l"(p));
    return a;
}
__device__ __forceinline__ void cp16(uint32_t dst, const void* src) {
    asm volatile("cp.async.ca.shared.global [%0], [%1], 16;" :: "r"(dst), "l"(src));
}
__device__ __forceinline__ void cp_commit() {
    asm volatile("cp.async.commit_group;");
}
__device__ __forceinline__ void ldmx4(uint32_t& r0, uint32_t& r1, uint32_t& r2, uint32_t& r3,
                                      uint32_t addr) {
    asm volatile("ldmatrix.sync.aligned.m8n8.x4.shared.b16 {%0,%1,%2,%3}, [%4];"
                 : "=r"(r0), "=r"(r1), "=r"(r2), "=r"(r3) : "r"(addr));
}
__device__ __forceinline__ void ldmx4t(uint32_t& r0, uint32_t& r1, uint32_t& r2, uint32_t& r3,
                                       uint32_t addr) {
    asm volatile("ldmatrix.sync.aligned.m8n8.x4.trans.shared.b16 {%0,%1,%2,%3}, [%4];"
                 : "=r"(r0), "=r"(r1), "=r"(r2), "=r"(r3) : "r"(addr));
}
// bf16 mma (attention)
__device__ __forceinline__ void mma16816(float* d,
                                         uint32_t a0, uint32_t a1, uint32_t a2, uint32_t a3,
                                         uint32_t b0, uint32_t b1) {
    asm volatile(
        "mma.sync.aligned.m16n8k16.row.col.f32.bf16.bf16.f32 "
        "{%0,%1,%2,%3}, {%4,%5,%6,%7}, {%8,%9}, {%0,%1,%2,%3};"
        : "+f"(d[0]), "+f"(d[1]), "+f"(d[2]), "+f"(d[3])
        : "r"(a0), "r"(a1), "r"(a2), "r"(a3), "r"(b0), "r"(b1));
}
// fp16 mma (GEMMs)
__device__ __forceinline__ void mma16816h(float* d,
                                          uint32_t a0, uint32_t a1, uint32_t a2, uint32_t a3,
                                          uint32_t b0, uint32_t b1) {
    asm volatile(
        "mma.sync.aligned.m16n8k16.row.col.f32.f16.f16.f32 "
        "{%0,%1,%2,%3}, {%4,%5,%6,%7}, {%8,%9}, {%0,%1,%2,%3};"
        : "+f"(d[0]), "+f"(d[1]), "+f"(d[2]), "+f"(d[3])
        : "r"(a0), "r"(a1), "r"(a2), "r"(a3), "r"(b0), "r"(b1));
}
// exp2 on the FMA pipe
__device__ __forceinline__ float exp2f_fast(float y) {
    y = fmaxf(y, -120.f);
    float t  = y + 12582912.f;
    float fl = t - 12582912.f;
    float fr = y - fl;
    float p = 0.0013333558f;
    p = fmaf(p, fr, 0.0096181291f);
    p = fmaf(p, fr, 0.0555041087f);
    p = fmaf(p, fr, 0.2402265069f);
    p = fmaf(p, fr, 0.6931471806f);
    p = fmaf(p, fr, 1.0f);
    int e = __float_as_int(t) << 23;
    return __int_as_float(__float_as_int(p) + e);
}

// ============================================================
// fp16 2-term GEMM (NT): C = (Ah + Al) * Bh^T  (+bias)
// CTA 128x128, BK=64, 16 k-tiles, double-buffered {Ah|Al|Bh} stages.
// ============================================================
#define KSEG 1024
#define NKT  16
#define OPND 16384               // 128 rows x 128B
#define STAGE3 (3*OPND)          // Ah + Al + Bh
#define SMEM_G2 (2*STAGE3)       // 96KB

template<int TAG>
__global__ __launch_bounds__(256, 2) void mma_gemm2(
    const __half* __restrict__ Ah, const __half* __restrict__ Al,
    const __half* __restrict__ Bh,
    float* __restrict__ C, const float* __restrict__ bias, int ldC)
{
    extern __shared__ char smem[];
    const uint32_t sbase = cvta_smem(smem);

    const int tid  = threadIdx.x;
    const int warp = tid >> 5;
    const int lane = tid & 31;
    const int wm   = warp >> 2;
    const int wn   = warp & 3;
    const int m0 = blockIdx.y * 128;
    const int n0 = blockIdx.x * 128;

    const int lrow = tid >> 3;
    const int lch  = tid & 7;

    auto issue_tile = [&](int kt, int stg) {
        const int kc = kt * 64;
        const uint32_t base = sbase + stg * STAGE3;
#pragma unroll
        for (int i = 0; i < 4; i++) {
            int row = lrow + 32 * i;
            uint32_t soff = (uint32_t)(row * 128 + ((lch * 16) ^ ((row & 7) << 4)));
            cp16(base + soff,            Ah + (size_t)(m0 + row) * KSEG + kc + lch * 8);
            cp16(base + OPND + soff,     Al + (size_t)(m0 + row) * KSEG + kc + lch * 8);
            cp16(base + 2 * OPND + soff, Bh + (size_t)(n0 + row) * KSEG + kc + lch * 8);
        }
        cp_commit();
    };

    float acc[4][4][4];
#pragma unroll
    for (int i = 0; i < 4; i++)
#pragma unroll
        for (int j = 0; j < 4; j++)
#pragma unroll
            for (int v = 0; v < 4; v++) acc[i][j][v] = 0.f;

    const int lrow16 = lane & 15;
    const int lchunk = lane >> 4;
    uint32_t aRow[4], aMask[4];
#pragma unroll
    for (int fi = 0; fi < 4; fi++) {
        int r = wm * 64 + fi * 16 + lrow16;
        aRow[fi]  = (uint32_t)(r * 128);
        aMask[fi] = (uint32_t)((r & 7) << 4);
    }
    uint32_t bRow[2], bMask[2];
#pragma unroll
    for (int nj = 0; nj < 2; nj++) {
        int r = wn * 32 + nj * 16 + lrow16;
        bRow[nj]  = (uint32_t)(r * 128 + 2 * OPND);
        bMask[nj] = (uint32_t)((r & 7) << 4);
    }

    issue_tile(0, 0);
    issue_tile(1, 1);

    for (int kt = 0; kt < NKT; kt++) {
        if (kt + 1 < NKT) asm volatile("cp.async.wait_group 1;");
        else              asm volatile("cp.async.wait_group 0;");
        __syncthreads();

        const uint32_t base = sbase + (kt & 1) * STAGE3;
#pragma unroll
        for (int ks = 0; ks < 4; ks++) {
            const uint32_t kb = (uint32_t)(ks * 32 + lchunk * 16);
            uint32_t ah[4][4], al[4][4], b[2][4];
#pragma unroll
            for (int fi = 0; fi < 4; fi++) {
                ldmx4(ah[fi][0], ah[fi][1], ah[fi][2], ah[fi][3],
                      base + aRow[fi] + (kb ^ aMask[fi]));
                ldmx4(al[fi][0], al[fi][1], al[fi][2], al[fi][3],
                      base + OPND + aRow[fi] + (kb ^ aMask[fi]));
            }
#pragma unroll
            for (int nj = 0; nj < 2; nj++)
                ldmx4(b[nj][0], b[nj][1], b[nj][2], b[nj][3],
                      base + bRow[nj] + (kb ^ bMask[nj]));
#pragma unroll
            for (int fi = 0; fi < 4; fi++) {
#pragma unroll
                for (int nj = 0; nj < 2; nj++) {
                    mma16816h(acc[fi][2*nj],   ah[fi][0], ah[fi][1], ah[fi][2], ah[fi][3],
                              b[nj][0], b[nj][2]);
                    mma16816h(acc[fi][2*nj+1], ah[fi][0], ah[fi][1], ah[fi][2], ah[fi][3],
                              b[nj][1], b[nj][3]);
                    mma16816h(acc[fi][2*nj],   al[fi][0], al[fi][1], al[fi][2], al[fi][3],
                              b[nj][0], b[nj][2]);
                    mma16816h(acc[fi][2*nj+1], al[fi][0], al[fi][1], al[fi][2], al[fi][3],
                              b[nj][1], b[nj][3]);
                }
            }
        }
        __syncthreads();
        if (kt + 2 < NKT) issue_tile(kt + 2, kt & 1);
    }

    const int mrow = m0 + wm * 64 + (lane >> 2);
    const int ncol = n0 + wn * 32 + (lane & 3) * 2;
#pragma unroll
    for (int fi = 0; fi < 4; fi++) {
#pragma unroll
        for (int nb = 0; nb < 4; nb++) {
            int r = mrow + fi * 16;
            int c = ncol + nb * 8;
            float b0 = 0.f, b1 = 0.f;
            if (bias) { b0 = bias[c]; b1 = bias[c + 1]; }
            *(float2*)&C[(size_t)r * ldC + c] =
                make_float2(acc[fi][nb][0] + b0, acc[fi][nb][1] + b1);
            *(float2*)&C[(size_t)(r + 8) * ldC + c] =
                make_float2(acc[fi][nb][2] + b0, acc[fi][nb][3] + b1);
        }
    }
}

// ============================================================
// fp32 -> fp16 exact 2-term split (hi + lo)
// ============================================================
__global__ __launch_bounds__(256) void split_h2(
    const float* __restrict__ in, __half* __restrict__ hi,
    __half* __restrict__ lo, int n4)
{
    int i = blockIdx.x * blockDim.x + threadIdx.x;
    if (i >= n4) return;
    float4 v = ((const float4*)in)[i];
    __half h[4], l[4];
    float x[4] = {v.x, v.y, v.z, v.w};
#pragma unroll
    for (int j = 0; j < 4; j++) {
        h[j] = __float2half_rn(x[j]);
        l[j] = __float2half_rn(x[j] - __half2float(h[j]));
    }
    ((uint2*)hi)[i] = *(const uint2*)h;
    ((uint2*)lo)[i] = *(const uint2*)l;
}

// fp32 -> fp16 round (weights: B operand, single term)
__global__ __launch_bounds__(256) void conv_h(
    const float* __restrict__ in, __half* __restrict__ hi, int n4)
{
    int i = blockIdx.x * blockDim.x + threadIdx.x;
    if (i >= n4) return;
    float4 v = ((const float4*)in)[i];
    __half h[4] = {__float2half_rn(v.x), __float2half_rn(v.y),
                   __float2half_rn(v.z), __float2half_rn(v.w)};
    ((uint2*)hi)[i] = *(const uint2*)h;
}

// ============================================================
// RMSNorm + rotary for q,k and raw split for v (bf16 hi/lo, unchanged).
// ============================================================
__global__ __launch_bounds__(256) void rms_rot_kernel(
    const float* __restrict__ qkv, const float* __restrict__ pos,
    const float* __restrict__ qw, const float* __restrict__ kw,
    __nv_bfloat16* __restrict__ qhi, __nv_bfloat16* __restrict__ qlo,
    __nv_bfloat16* __restrict__ khi, __nv_bfloat16* __restrict__ klo,
    __nv_bfloat16* __restrict__ vhi, __nv_bfloat16* __restrict__ vlo)
{
    int wgi  = blockIdx.x * (blockDim.x >> 5) + (threadIdx.x >> 5);
    int lane = threadIdx.x & 31;
    int n   =  wgi        & (NSEQ - 1);
    int h   = (wgi >> 11) & (NHEAD - 1);
    int b   = (wgi >> 15) & 1;
    int sel =  wgi >> 16;                     // 0=q, 1=k, 2=v

    const float* src = qkv + (size_t)(b * NSEQ + n) * QKV_F + sel * DIMC + h * HDIM + 2 * lane;
    float2 v = *(const float2*)src;

    float o0, o1;
    if (sel < 2) {
        float ss = v.x * v.x + v.y * v.y;
#pragma unroll
        for (int o = 16; o; o >>= 1) ss += __shfl_xor_sync(0xffffffffu, ss, o);
        float r = rsqrtf(ss * (1.f / HDIM) + 1e-6f);
        const float* w = sel ? kw : qw;
        float xr = v.x * r * w[2 * lane];
        float xi = v.y * r * w[2 * lane + 1];
        float ang = pos[n * (HDIM / 2) + lane];
        float sn, cs;
        __sincosf(ang, &sn, &cs);
        o0 = xr * cs - xi * sn;
        o1 = xr * sn + xi * cs;
        if (!sel) { o0 *= 0.125f; o1 *= 0.125f; }
    } else {
        o0 = v.x; o1 = v.y;
    }

    __nv_bfloat16* hi = (sel == 0) ? qhi : (sel == 1) ? khi : vhi;
    __nv_bfloat16* lo = (sel == 0) ? qlo : (sel == 1) ? klo : vlo;
    size_t dofs = (size_t)((b * NHEAD + h) * NSEQ + n) * HDIM + 2 * lane;
    __nv_bfloat162 hp = __floats2bfloat162_rn(o0, o1);
    __nv_bfloat162 lp = __floats2bfloat162_rn(o0 - __bfloat162float(hp.x),
                                              o1 - __bfloat162float(hp.y));
    *(__nv_bfloat162*)(hi + dofs) = hp;
    *(__nv_bfloat162*)(lo + dofs) = lp;
}

// ============================================================
// Tensor-core flash attention (bf16 3-term, FMA softmax),
// double-buffered K/V; epilogue emits fp16 hi/lo for proj.
// ============================================================
#define ATTN_STAGE 32768
#define ATTN_SMEM  (2*ATTN_STAGE)

__global__ __launch_bounds__(256) void attn_mma(
    const __nv_bfloat16* __restrict__ Qh, const __nv_bfloat16* __restrict__ Ql,
    const __nv_bfloat16* __restrict__ Kh, const __nv_bfloat16* __restrict__ Kl,
    const __nv_bfloat16* __restrict__ Vh, const __nv_bfloat16* __restrict__ Vl,
    __half* __restrict__ OHi, __half* __restrict__ OLo)
{
    extern __shared__ __align__(16) char sm[];
    const uint32_t sb = cvta_smem(sm);

    const int tid = threadIdx.x, warp = tid >> 5, lane = tid & 31;
    const int m0 = blockIdx.x * 128;
    const int h = blockIdx.y, b = blockIdx.z;
    const size_t hoff = (size_t)((b * NHEAD + h) * NSEQ);

    const int lrow16 = lane & 15, lchunk = lane >> 4;

    // ---- stage Q (hi then lo) through smem, build A-frags ----
    uint32_t qfh[4][4], qfl[4][4];
    {
        const __nv_bfloat16* Qsrc[2] = {Qh, Ql};
        const int r = warp * 16 + lrow16;
        const uint32_t rb = (uint32_t)(r * 128), msk = (uint32_t)((r & 7) << 4);
        for (int pass = 0; pass < 2; pass++) {
#pragma unroll
            for (int i = 0; i < 4; i++) {
                int id = tid + 256 * i;
                int row = id >> 3, ch = id & 7;
                *(uint4*)(sm + row * 128 + ((ch * 16) ^ ((row & 7) << 4))) =
                    *(const uint4*)(Qsrc[pass] + (hoff + m0 + row) * HDIM + ch * 8);
            }
            __syncthreads();
#pragma unroll
            for (int kc = 0; kc < 4; kc++) {
                uint32_t addr = sb + rb + (((uint32_t)(kc * 32 + lchunk * 16)) ^ msk);
                if (pass == 0) ldmx4(qfh[kc][0], qfh[kc][1], qfh[kc][2], qfh[kc][3], addr);
                else           ldmx4(qfl[kc][0], qfl[kc][1], qfl[kc][2], qfl[kc][3], addr);
            }
            __syncthreads();
        }
    }

    float o[8][4];
#pragma unroll
    for (int i = 0; i < 8; i++)
#pragma unroll
        for (int j = 0; j < 4; j++) o[i][j] = 0.f;
    float om0 = -1e30f, om1 = -1e30f, ol0 = 0.f, ol1 = 0.f;

    const __nv_bfloat16* srcs[4] = {Kh, Kl, Vh, Vl};

    auto issue_kv = [&](int j0, int stg) {
#pragma unroll
        for (int i = 0; i < 8; i++) {
            int id = tid + 256 * i;
            int arr = id >> 9, row = (id >> 3) & 63, ch = id & 7;
            cp16(sb + stg * ATTN_STAGE + arr * 8192 +
                     (uint32_t)(row * 128 + ((ch * 16) ^ ((row & 7) << 4))),
                 srcs[arr] + (hoff + j0 + row) * HDIM + ch * 8);
        }
        cp_commit();
    };

    issue_kv(0, 0);

    const int NT = NSEQ / 64;
    for (int t = 0; t < NT; t++) {
        const int buf = t & 1;
        if (t + 1 < NT) {
            issue_kv((t + 1) * 64, buf ^ 1);
            asm volatile("cp.async.wait_group 1;");
        } else {
            asm volatile("cp.async.wait_group 0;");
        }
        __syncthreads();
        const uint32_t stb = sb + buf * ATTN_STAGE;

        // ---- S = qh*kh + ql*kh + qh*kl ----
        float s[8][4];
#pragma unroll
        for (int i = 0; i < 8; i++)
#pragma unroll
            for (int j = 0; j < 4; j++) s[i][j] = 0.f;
#pragma unroll
        for (int ng = 0; ng < 4; ng++) {
            const int r = ng * 16 + lrow16;
            const uint32_t rb = (uint32_t)(r * 128), msk = (uint32_t)((r & 7) << 4);
#pragma unroll
            for (int kc = 0; kc < 4; kc++) {
                const uint32_t co = (((uint32_t)(kc * 32 + lchunk * 16)) ^ msk);
                uint32_t k0, k1, k2, k3;
                ldmx4(k0, k1, k2, k3, stb + rb + co);               // khi
                mma16816(s[2*ng],   qfh[kc][0], qfh[kc][1], qfh[kc][2], qfh[kc][3], k0, k2);
                mma16816(s[2*ng+1], qfh[kc][0], qfh[kc][1], qfh[kc][2], qfh[kc][3], k1, k3);
                mma16816(s[2*ng],   qfl[kc][0], qfl[kc][1], qfl[kc][2], qfl[kc][3], k0, k2);
                mma16816(s[2*ng+1], qfl[kc][0], qfl[kc][1], qfl[kc][2], qfl[kc][3], k1, k3);
                ldmx4(k0, k1, k2, k3, stb + 8192 + rb + co);        // klo
                mma16816(s[2*ng],   qfh[kc][0], qfh[kc][1], qfh[kc][2], qfh[kc][3], k0, k2);
                mma16816(s[2*ng+1], qfh[kc][0], qfh[kc][1], qfh[kc][2], qfh[kc][3], k1, k3);
            }
        }

        // ---- online softmax (FMA exp) ----
        float tm0 = -1e30f, tm1 = -1e30f;
#pragma unroll
        for (int nb = 0; nb < 8; nb++) {
            tm0 = fmaxf(tm0, fmaxf(s[nb][0], s[nb][1]));
            tm1 = fmaxf(tm1, fmaxf(s[nb][2], s[nb][3]));
        }
        tm0 = fmaxf(tm0, __shfl_xor_sync(0xffffffffu, tm0, 1));
        tm0 = fmaxf(tm0, __shfl_xor_sync(0xffffffffu, tm0, 2));
        tm1 = fmaxf(tm1, __shfl_xor_sync(0xffffffffu, tm1, 1));
        tm1 = fmaxf(tm1, __shfl_xor_sync(0xffffffffu, tm1, 2));
        float mn0 = fmaxf(om0, tm0), mn1 = fmaxf(om1, tm1);
        float c0 = exp2f_fast((om0 - mn0) * L2E);
        float c1 = exp2f_fast((om1 - mn1) * L2E);
        om0 = mn0; om1 = mn1;
        const float nm0 = -mn0 * L2E, nm1 = -mn1 * L2E;

        float rs0 = 0.f, rs1 = 0.f;
        uint32_t pH01[8], pH23[8], pL01[8], pL23[8];
#pragma unroll
        for (int nb = 0; nb < 8; nb++) {
            float p0 = exp2f_fast(fmaf(s[nb][0], L2E, nm0));
            float p1 = exp2f_fast(fmaf(s[nb][1], L2E, nm0));
            float p2 = exp2f_fast(fmaf(s[nb][2], L2E, nm1));
            float p3 = exp2f_fast(fmaf(s[nb][3], L2E, nm1));
            rs0 += p0 + p1; rs1 += p2 + p3;
            __nv_bfloat162 h01 = __floats2bfloat162_rn(p0, p1);
            __nv_bfloat162 h23 = __floats2bfloat162_rn(p2, p3);
            __nv_bfloat162 l01 = __floats2bfloat162_rn(p0 - __bfloat162float(h01.x),
                                                       p1 - __bfloat162float(h01.y));
            __nv_bfloat162 l23 = __floats2bfloat162_rn(p2 - __bfloat162float(h23.x),
                                                       p3 - __bfloat162float(h23.y));
            pH01[nb] = *(uint32_t*)&h01; pH23[nb] = *(uint32_t*)&h23;
            pL01[nb] = *(uint32_t*)&l01; pL23[nb] = *(uint32_t*)&l23;
        }
        ol0 = fmaf(ol0, c0, rs0);
        ol1 = fmaf(ol1, c1, rs1);
#pragma unroll
        for (int db = 0; db < 8; db++) {
            o[db][0] *= c0; o[db][1] *= c0; o[db][2] *= c1; o[db][3] *= c1;
        }

        // ---- O += ph*vh + pl*vh + ph*vl  (V via ldmatrix.trans) ----
        const int tq = lane >> 3;
        const int krow_base = (tq & 1) * 8 + (lane & 7);
        const int ncol_base = (tq >> 1) * 8;
#pragma unroll
        for (int kc = 0; kc < 4; kc++) {
            const uint32_t ah0 = pH01[2*kc], ah1 = pH23[2*kc];
            const uint32_t ah2 = pH01[2*kc+1], ah3 = pH23[2*kc+1];
            const uint32_t al0 = pL01[2*kc], al1 = pL23[2*kc];
            const uint32_t al2 = pL01[2*kc+1], al3 = pL23[2*kc+1];
            const int krow = kc * 16 + krow_base;
            const uint32_t roff = (uint32_t)(krow * 128);
            const uint32_t rmsk = (uint32_t)((krow & 7) << 4);
#pragma unroll
            for (int dg = 0; dg < 4; dg++) {
                const uint32_t aoff = roff + (((uint32_t)((dg * 16 + ncol_base) * 2)) ^ rmsk);
                uint32_t v0, v1, v2, v3;
                ldmx4t(v0, v1, v2, v3, stb + 16384 + aoff);          // vhi
                mma16816(o[2*dg],   ah0, ah1, ah2, ah3, v0, v1);
                mma16816(o[2*dg+1], ah0, ah1, ah2, ah3, v2, v3);
                mma16816(o[2*dg],   al0, al1, al2, al3, v0, v1);
                mma16816(o[2*dg+1], al0, al1, al2, al3, v2, v3);
                ldmx4t(v0, v1, v2, v3, stb + 24576 + aoff);          // vlo
                mma16816(o[2*dg],   ah0, ah1, ah2, ah3, v0, v1);
                mma16816(o[2*dg+1], ah0, ah1, ah2, ah3, v2, v3);
            }
        }
        __syncthreads();
    }

    // ---- row sum lives across the lane quad -> reduce before normalizing ----
    ol0 += __shfl_xor_sync(0xffffffffu, ol0, 1);
    ol0 += __shfl_xor_sync(0xffffffffu, ol0, 2);
    ol1 += __shfl_xor_sync(0xffffffffu, ol1, 1);
    ol1 += __shfl_xor_sync(0xffffffffu, ol1, 2);

    // ---- epilogue: normalize, split to fp16 hi/lo, store [B,N,C] ----
    const float i0 = 1.f / ol0, i1 = 1.f / ol1;
    const int r0 = m0 + warp * 16 + (lane >> 2), r1 = r0 + 8;
    const int cb = h * HDIM + (lane & 3) * 2;
#pragma unroll
    for (int db = 0; db < 8; db++) {
        const int c = cb + db * 8;
        float a0 = o[db][0] * i0, a1 = o[db][1] * i0;
        float a2 = o[db][2] * i1, a3 = o[db][3] * i1;
        __half h0 = __float2half_rn(a0), h1 = __float2half_rn(a1);
        __half h2 = __float2half_rn(a2), h3 = __float2half_rn(a3);
        __half l0 = __float2half_rn(a0 - __half2float(h0));
        __half l1 = __float2half_rn(a1 - __half2float(h1));
        __half l2 = __float2half_rn(a2 - __half2float(h2));
        __half l3 = __float2half_rn(a3 - __half2float(h3));
        __half hp01[2] = {h0, h1}, hp23[2] = {h2, h3};
        __half lp01[2] = {l0, l1}, lp23[2] = {l2, l3};
        *(uint32_t*)(OHi + (size_t)(b * NSEQ + r0) * DIMC + c) = *(uint32_t*)hp01;
        *(uint32_t*)(OLo + (size_t)(b * NSEQ + r0) * DIMC + c) = *(uint32_t*)lp01;
        *(uint32_t*)(OHi + (size_t)(b * NSEQ + r1) * DIMC + c) = *(uint32_t*)hp23;
        *(uint32_t*)(OLo + (size_t)(b * NSEQ + r1) * DIMC + c) = *(uint32_t*)lp23;
    }
}

// ============================================================
extern "C" void kernel_launch(void* const* d_in, const int* in_sizes, int n_in,
                              void* d_out, int out_size)
{
    const float* x      = (const float*)d_in[0];
    const float* pos    = (const float*)d_in[1];
    const float* qkv_w  = (const float*)d_in[2];
    const float* qnw    = (const float*)d_in[3];
    const float* knw    = (const float*)d_in[4];
    const float* proj_w = (const float*)d_in[5];
    const float* proj_b = (const float*)d_in[6];
    float* out = (float*)d_out;

    float *qkv;
    __half *xhi, *xlo, *whi, *phi, *ahi, *alo;
    __nv_bfloat16 *qhi, *qlo, *khi, *klo, *vhi, *vlo;
    cudaGetSymbolAddress((void**)&qkv, g_qkv);
    cudaGetSymbolAddress((void**)&xhi, g_xhi);  cudaGetSymbolAddress((void**)&xlo, g_xlo);
    cudaGetSymbolAddress((void**)&whi, g_whi);
    cudaGetSymbolAddress((void**)&phi, g_phi);
    cudaGetSymbolAddress((void**)&ahi, g_ahi);  cudaGetSymbolAddress((void**)&alo, g_alo);
    cudaGetSymbolAddress((void**)&qhi, g_qhi);  cudaGetSymbolAddress((void**)&qlo, g_qlo);
    cudaGetSymbolAddress((void**)&khi, g_khi);  cudaGetSymbolAddress((void**)&klo, g_klo);
    cudaGetSymbolAddress((void**)&vhi, g_vhi);  cudaGetSymbolAddress((void**)&vlo, g_vlo);

    cudaFuncSetAttribute(mma_gemm2<0>, cudaFuncAttributeMaxDynamicSharedMemorySize, SMEM_G2);
    cudaFuncSetAttribute(mma_gemm2<1>, cudaFuncAttributeMaxDynamicSharedMemorySize, SMEM_G2);
    cudaFuncSetAttribute(attn_mma, cudaFuncAttributeMaxDynamicSharedMemorySize, ATTN_SMEM);

    // 0) fp16 splits/rounds of inputs
    split_h2<<<(ROWS * DIMC / 4 + 255) / 256, 256>>>(x, xhi, xlo, ROWS * DIMC / 4);
    conv_h<<<(QKV_F * DIMC / 4 + 255) / 256, 256>>>(qkv_w, whi, QKV_F * DIMC / 4);
    conv_h<<<(DIMC * DIMC / 4 + 255) / 256, 256>>>(proj_w, phi, DIMC * DIMC / 4);

    // 1) QKV projection (fp16 2-term tensor cores)
    mma_gemm2<0><<<dim3(QKV_F / 128, ROWS / 128), 256, SMEM_G2>>>(
        xhi, xlo, whi, qkv, nullptr, QKV_F);

    // 2) RMSNorm + rotary (q,k) and split (v) -> bf16 hi/lo [B,H,N,D]
    rms_rot_kernel<<<(3 * BQ * NHEAD * NSEQ) / 8, 256>>>(
        qkv, pos, qnw, knw, qhi, qlo, khi, klo, vhi, vlo);

    // 3) Tensor-core flash attention (bf16 3-term) -> fp16 hi/lo [B,N,C]
    attn_mma<<<dim3(NSEQ / 128, NHEAD, BQ), 256, ATTN_SMEM>>>(
        qhi, qlo, khi, klo, vhi, vlo, ahi, alo);

    // 4) proj (fp16 2-term tensor cores) + bias
    mma_gemm2<1><<<dim3(DIMC / 128, ROWS / 128), 256, SMEM_G2>>>(
        ahi, alo, phi, out, proj_b, DIMC);
}

// round 12
// speedup vs baseline: 5.8393x; 1.1749x over previous
#include <cuda_runtime.h>
#include <cuda_fp16.h>
#include <math.h>
#include <stdint.h>

#define DIMC  1024
#define NHEAD 16
#define HDIM  64
#define BQ    2
#define NSEQ  2048
#define ROWS  (BQ*NSEQ)      // 4096
#define QKV_F (3*DIMC)       // 3072
#define L2E   1.4426950408889634f

// ---- scratch (no allocations allowed) ----
__device__ float g_qkv [ROWS * QKV_F];
__device__ __half g_xhi[ROWS * DIMC];
__device__ __half g_xlo[ROWS * DIMC];
__device__ __half g_whi[QKV_F * DIMC];
__device__ __half g_phi[DIMC * DIMC];
__device__ __half g_ahi[ROWS * DIMC];
__device__ __half g_alo[ROWS * DIMC];
// [B,H,N,D] fp16 operands for attention: Q 2-term, K/V single-rounded
__device__ __half g_qhi[ROWS * DIMC];
__device__ __half g_qlo[ROWS * DIMC];
__device__ __half g_khi[ROWS * DIMC];
__device__ __half g_vhi[ROWS * DIMC];

__device__ __forceinline__ uint32_t cvta_smem(const void* p) {
    uint32_t a;
    asm("{ .reg .u64 t; cvta.to.shared.u64 t, %1; cvt.u32.u64 %0, t; }" : "=r"(a) : "l"(p));
    return a;
}
__device__ __forceinline__ void cp16(uint32_t dst, const void* src) {
    asm volatile("cp.async.ca.shared.global [%0], [%1], 16;" :: "r"(dst), "l"(src));
}
__device__ __forceinline__ void cp_commit() {
    asm volatile("cp.async.commit_group;");
}
__device__ __forceinline__ void ldmx4(uint32_t& r0, uint32_t& r1, uint32_t& r2, uint32_t& r3,
                                      uint32_t addr) {
    asm volatile("ldmatrix.sync.aligned.m8n8.x4.shared.b16 {%0,%1,%2,%3}, [%4];"
                 : "=r"(r0), "=r"(r1), "=r"(r2), "=r"(r3) : "r"(addr));
}
__device__ __forceinline__ void ldmx4t(uint32_t& r0, uint32_t& r1, uint32_t& r2, uint32_t& r3,
                                       uint32_t addr) {
    asm volatile("ldmatrix.sync.aligned.m8n8.x4.trans.shared.b16 {%0,%1,%2,%3}, [%4];"
                 : "=r"(r0), "=r"(r1), "=r"(r2), "=r"(r3) : "r"(addr));
}
// fp16 mma
__device__ __forceinline__ void mma16816h(float* d,
                                          uint32_t a0, uint32_t a1, uint32_t a2, uint32_t a3,
                                          uint32_t b0, uint32_t b1) {
    asm volatile(
        "mma.sync.aligned.m16n8k16.row.col.f32.f16.f16.f32 "
        "{%0,%1,%2,%3}, {%4,%5,%6,%7}, {%8,%9}, {%0,%1,%2,%3};"
        : "+f"(d[0]), "+f"(d[1]), "+f"(d[2]), "+f"(d[3])
        : "r"(a0), "r"(a1), "r"(a2), "r"(a3), "r"(b0), "r"(b1));
}
// exp2 on the FMA pipe
__device__ __forceinline__ float exp2f_fast(float y) {
    y = fmaxf(y, -120.f);
    float t  = y + 12582912.f;
    float fl = t - 12582912.f;
    float fr = y - fl;
    float p = 0.0013333558f;
    p = fmaf(p, fr, 0.0096181291f);
    p = fmaf(p, fr, 0.0555041087f);
    p = fmaf(p, fr, 0.2402265069f);
    p = fmaf(p, fr, 0.6931471806f);
    p = fmaf(p, fr, 1.0f);
    int e = __float_as_int(t) << 23;
    return __int_as_float(__float_as_int(p) + e);
}

// ============================================================
// fp16 2-term GEMM (NT): C = (Ah + Al) * Bh^T  (+bias)
// ============================================================
#define KSEG 1024
#define NKT  16
#define OPND 16384
#define STAGE3 (3*OPND)
#define SMEM_G2 (2*STAGE3)

template<int TAG>
__global__ __launch_bounds__(256, 2) void mma_gemm2(
    const __half* __restrict__ Ah, const __half* __restrict__ Al,
    const __half* __restrict__ Bh,
    float* __restrict__ C, const float* __restrict__ bias, int ldC)
{
    extern __shared__ char smem[];
    const uint32_t sbase = cvta_smem(smem);

    const int tid  = threadIdx.x;
    const int warp = tid >> 5;
    const int lane = tid & 31;
    const int wm   = warp >> 2;
    const int wn   = warp & 3;
    const int m0 = blockIdx.y * 128;
    const int n0 = blockIdx.x * 128;

    const int lrow = tid >> 3;
    const int lch  = tid & 7;

    auto issue_tile = [&](int kt, int stg) {
        const int kc = kt * 64;
        const uint32_t base = sbase + stg * STAGE3;
#pragma unroll
        for (int i = 0; i < 4; i++) {
            int row = lrow + 32 * i;
            uint32_t soff = (uint32_t)(row * 128 + ((lch * 16) ^ ((row & 7) << 4)));
            cp16(base + soff,            Ah + (size_t)(m0 + row) * KSEG + kc + lch * 8);
            cp16(base + OPND + soff,     Al + (size_t)(m0 + row) * KSEG + kc + lch * 8);
            cp16(base + 2 * OPND + soff, Bh + (size_t)(n0 + row) * KSEG + kc + lch * 8);
        }
        cp_commit();
    };

    float acc[4][4][4];
#pragma unroll
    for (int i = 0; i < 4; i++)
#pragma unroll
        for (int j = 0; j < 4; j++)
#pragma unroll
            for (int v = 0; v < 4; v++) acc[i][j][v] = 0.f;

    const int lrow16 = lane & 15;
    const int lchunk = lane >> 4;
    uint32_t aRow[4], aMask[4];
#pragma unroll
    for (int fi = 0; fi < 4; fi++) {
        int r = wm * 64 + fi * 16 + lrow16;
        aRow[fi]  = (uint32_t)(r * 128);
        aMask[fi] = (uint32_t)((r & 7) << 4);
    }
    uint32_t bRow[2], bMask[2];
#pragma unroll
    for (int nj = 0; nj < 2; nj++) {
        int r = wn * 32 + nj * 16 + lrow16;
        bRow[nj]  = (uint32_t)(r * 128 + 2 * OPND);
        bMask[nj] = (uint32_t)((r & 7) << 4);
    }

    issue_tile(0, 0);
    issue_tile(1, 1);

    for (int kt = 0; kt < NKT; kt++) {
        if (kt + 1 < NKT) asm volatile("cp.async.wait_group 1;");
        else              asm volatile("cp.async.wait_group 0;");
        __syncthreads();

        const uint32_t base = sbase + (kt & 1) * STAGE3;
#pragma unroll
        for (int ks = 0; ks < 4; ks++) {
            const uint32_t kb = (uint32_t)(ks * 32 + lchunk * 16);
            uint32_t ah[4][4], al[4][4], b[2][4];
#pragma unroll
            for (int fi = 0; fi < 4; fi++) {
                ldmx4(ah[fi][0], ah[fi][1], ah[fi][2], ah[fi][3],
                      base + aRow[fi] + (kb ^ aMask[fi]));
                ldmx4(al[fi][0], al[fi][1], al[fi][2], al[fi][3],
                      base + OPND + aRow[fi] + (kb ^ aMask[fi]));
            }
#pragma unroll
            for (int nj = 0; nj < 2; nj++)
                ldmx4(b[nj][0], b[nj][1], b[nj][2], b[nj][3],
                      base + bRow[nj] + (kb ^ bMask[nj]));
#pragma unroll
            for (int fi = 0; fi < 4; fi++) {
#pragma unroll
                for (int nj = 0; nj < 2; nj++) {
                    mma16816h(acc[fi][2*nj],   ah[fi][0], ah[fi][1], ah[fi][2], ah[fi][3],
                              b[nj][0], b[nj][2]);
                    mma16816h(acc[fi][2*nj+1], ah[fi][0], ah[fi][1], ah[fi][2], ah[fi][3],
                              b[nj][1], b[nj][3]);
                    mma16816h(acc[fi][2*nj],   al[fi][0], al[fi][1], al[fi][2], al[fi][3],
                              b[nj][0], b[nj][2]);
                    mma16816h(acc[fi][2*nj+1], al[fi][0], al[fi][1], al[fi][2], al[fi][3],
                              b[nj][1], b[nj][3]);
                }
            }
        }
        __syncthreads();
        if (kt + 2 < NKT) issue_tile(kt + 2, kt & 1);
    }

    const int mrow = m0 + wm * 64 + (lane >> 2);
    const int ncol = n0 + wn * 32 + (lane & 3) * 2;
#pragma unroll
    for (int fi = 0; fi < 4; fi++) {
#pragma unroll
        for (int nb = 0; nb < 4; nb++) {
            int r = mrow + fi * 16;
            int c = ncol + nb * 8;
            float b0 = 0.f, b1 = 0.f;
            if (bias) { b0 = bias[c]; b1 = bias[c + 1]; }
            *(float2*)&C[(size_t)r * ldC + c] =
                make_float2(acc[fi][nb][0] + b0, acc[fi][nb][1] + b1);
            *(float2*)&C[(size_t)(r + 8) * ldC + c] =
                make_float2(acc[fi][nb][2] + b0, acc[fi][nb][3] + b1);
        }
    }
}

// ============================================================
// fp32 -> fp16 exact 2-term split
// ============================================================
__global__ __launch_bounds__(256) void split_h2(
    const float* __restrict__ in, __half* __restrict__ hi,
    __half* __restrict__ lo, int n4)
{
    int i = blockIdx.x * blockDim.x + threadIdx.x;
    if (i >= n4) return;
    float4 v = ((const float4*)in)[i];
    __half h[4], l[4];
    float x[4] = {v.x, v.y, v.z, v.w};
#pragma unroll
    for (int j = 0; j < 4; j++) {
        h[j] = __float2half_rn(x[j]);
        l[j] = __float2half_rn(x[j] - __half2float(h[j]));
    }
    ((uint2*)hi)[i] = *(const uint2*)h;
    ((uint2*)lo)[i] = *(const uint2*)l;
}

// fp32 -> fp16 single round
__global__ __launch_bounds__(256) void conv_h(
    const float* __restrict__ in, __half* __restrict__ hi, int n4)
{
    int i = blockIdx.x * blockDim.x + threadIdx.x;
    if (i >= n4) return;
    float4 v = ((const float4*)in)[i];
    __half h[4] = {__float2half_rn(v.x), __float2half_rn(v.y),
                   __float2half_rn(v.z), __float2half_rn(v.w)};
    ((uint2*)hi)[i] = *(const uint2*)h;
}

// ============================================================
// RMSNorm + rotary: q -> fp16 2-term; k,v -> fp16 single round.
// ============================================================
__global__ __launch_bounds__(256) void rms_rot_kernel(
    const float* __restrict__ qkv, const float* __restrict__ pos,
    const float* __restrict__ qw, const float* __restrict__ kw,
    __half* __restrict__ qhi, __half* __restrict__ qlo,
    __half* __restrict__ khi, __half* __restrict__ vhi)
{
    int wgi  = blockIdx.x * (blockDim.x >> 5) + (threadIdx.x >> 5);
    int lane = threadIdx.x & 31;
    int n   =  wgi        & (NSEQ - 1);
    int h   = (wgi >> 11) & (NHEAD - 1);
    int b   = (wgi >> 15) & 1;
    int sel =  wgi >> 16;                     // 0=q, 1=k, 2=v

    const float* src = qkv + (size_t)(b * NSEQ + n) * QKV_F + sel * DIMC + h * HDIM + 2 * lane;
    float2 v = *(const float2*)src;

    float o0, o1;
    if (sel < 2) {
        float ss = v.x * v.x + v.y * v.y;
#pragma unroll
        for (int o = 16; o; o >>= 1) ss += __shfl_xor_sync(0xffffffffu, ss, o);
        float r = rsqrtf(ss * (1.f / HDIM) + 1e-6f);
        const float* w = sel ? kw : qw;
        float xr = v.x * r * w[2 * lane];
        float xi = v.y * r * w[2 * lane + 1];
        float ang = pos[n * (HDIM / 2) + lane];
        float sn, cs;
        __sincosf(ang, &sn, &cs);
        o0 = xr * cs - xi * sn;
        o1 = xr * sn + xi * cs;
        if (!sel) { o0 *= 0.125f; o1 *= 0.125f; }
    } else {
        o0 = v.x; o1 = v.y;
    }

    size_t dofs = (size_t)((b * NHEAD + h) * NSEQ + n) * HDIM + 2 * lane;
    __half h0 = __float2half_rn(o0), h1 = __float2half_rn(o1);
    __half hp[2] = {h0, h1};
    if (sel == 0) {
        __half l0 = __float2half_rn(o0 - __half2float(h0));
        __half l1 = __float2half_rn(o1 - __half2float(h1));
        __half lp[2] = {l0, l1};
        *(uint32_t*)(qhi + dofs) = *(uint32_t*)hp;
        *(uint32_t*)(qlo + dofs) = *(uint32_t*)lp;
    } else {
        __half* dst = (sel == 1) ? khi : vhi;
        *(uint32_t*)(dst + dofs) = *(uint32_t*)hp;
    }
}

// ============================================================
// Tensor-core flash attention, fp16 2-term:
// S = (Qh+Ql)*Kh^T ; O = (Ph+Pl)*Vh. Double-buffered 16KB K/V stages.
// ============================================================
#define ATTN_STAGE 16384           // Kh (8KB) + Vh (8KB)
#define ATTN_SMEM  (2*ATTN_STAGE)

__global__ __launch_bounds__(256) void attn_mma(
    const __half* __restrict__ Qh, const __half* __restrict__ Ql,
    const __half* __restrict__ Kh, const __half* __restrict__ Vh,
    __half* __restrict__ OHi, __half* __restrict__ OLo)
{
    extern __shared__ __align__(16) char sm[];
    const uint32_t sb = cvta_smem(sm);

    const int tid = threadIdx.x, warp = tid >> 5, lane = tid & 31;
    const int m0 = blockIdx.x * 128;
    const int h = blockIdx.y, b = blockIdx.z;
    const size_t hoff = (size_t)((b * NHEAD + h) * NSEQ);

    const int lrow16 = lane & 15, lchunk = lane >> 4;

    // ---- stage Q (hi then lo) through smem, build A-frags ----
    uint32_t qfh[4][4], qfl[4][4];
    {
        const __half* Qsrc[2] = {Qh, Ql};
        const int r = warp * 16 + lrow16;
        const uint32_t rb = (uint32_t)(r * 128), msk = (uint32_t)((r & 7) << 4);
        for (int pass = 0; pass < 2; pass++) {
#pragma unroll
            for (int i = 0; i < 4; i++) {
                int id = tid + 256 * i;
                int row = id >> 3, ch = id & 7;
                *(uint4*)(sm + row * 128 + ((ch * 16) ^ ((row & 7) << 4))) =
                    *(const uint4*)(Qsrc[pass] + (hoff + m0 + row) * HDIM + ch * 8);
            }
            __syncthreads();
#pragma unroll
            for (int kc = 0; kc < 4; kc++) {
                uint32_t addr = sb + rb + (((uint32_t)(kc * 32 + lchunk * 16)) ^ msk);
                if (pass == 0) ldmx4(qfh[kc][0], qfh[kc][1], qfh[kc][2], qfh[kc][3], addr);
                else           ldmx4(qfl[kc][0], qfl[kc][1], qfl[kc][2], qfl[kc][3], addr);
            }
            __syncthreads();
        }
    }

    float o[8][4];
#pragma unroll
    for (int i = 0; i < 8; i++)
#pragma unroll
        for (int j = 0; j < 4; j++) o[i][j] = 0.f;
    float om0 = -1e30f, om1 = -1e30f, ol0 = 0.f, ol1 = 0.f;

    const __half* srcs[2] = {Kh, Vh};

    auto issue_kv = [&](int j0, int stg) {
#pragma unroll
        for (int i = 0; i < 4; i++) {
            int id = tid + 256 * i;
            int arr = id >> 9, row = (id >> 3) & 63, ch = id & 7;
            cp16(sb + stg * ATTN_STAGE + arr * 8192 +
                     (uint32_t)(row * 128 + ((ch * 16) ^ ((row & 7) << 4))),
                 srcs[arr] + (hoff + j0 + row) * HDIM + ch * 8);
        }
        cp_commit();
    };

    issue_kv(0, 0);

    const int NT = NSEQ / 64;
    for (int t = 0; t < NT; t++) {
        const int buf = t & 1;
        if (t + 1 < NT) {
            issue_kv((t + 1) * 64, buf ^ 1);
            asm volatile("cp.async.wait_group 1;");
        } else {
            asm volatile("cp.async.wait_group 0;");
        }
        __syncthreads();
        const uint32_t stb = sb + buf * ATTN_STAGE;

        // ---- S = (Qh + Ql) * Kh^T ----
        float s[8][4];
#pragma unroll
        for (int i = 0; i < 8; i++)
#pragma unroll
            for (int j = 0; j < 4; j++) s[i][j] = 0.f;
#pragma unroll
        for (int ng = 0; ng < 4; ng++) {
            const int r = ng * 16 + lrow16;
            const uint32_t rb = (uint32_t)(r * 128), msk = (uint32_t)((r & 7) << 4);
#pragma unroll
            for (int kc = 0; kc < 4; kc++) {
                const uint32_t co = (((uint32_t)(kc * 32 + lchunk * 16)) ^ msk);
                uint32_t k0, k1, k2, k3;
                ldmx4(k0, k1, k2, k3, stb + rb + co);
                mma16816h(s[2*ng],   qfh[kc][0], qfh[kc][1], qfh[kc][2], qfh[kc][3], k0, k2);
                mma16816h(s[2*ng+1], qfh[kc][0], qfh[kc][1], qfh[kc][2], qfh[kc][3], k1, k3);
                mma16816h(s[2*ng],   qfl[kc][0], qfl[kc][1], qfl[kc][2], qfl[kc][3], k0, k2);
                mma16816h(s[2*ng+1], qfl[kc][0], qfl[kc][1], qfl[kc][2], qfl[kc][3], k1, k3);
            }
        }

        // ---- online softmax (FMA exp) ----
        float tm0 = -1e30f, tm1 = -1e30f;
#pragma unroll
        for (int nb = 0; nb < 8; nb++) {
            tm0 = fmaxf(tm0, fmaxf(s[nb][0], s[nb][1]));
            tm1 = fmaxf(tm1, fmaxf(s[nb][2], s[nb][3]));
        }
        tm0 = fmaxf(tm0, __shfl_xor_sync(0xffffffffu, tm0, 1));
        tm0 = fmaxf(tm0, __shfl_xor_sync(0xffffffffu, tm0, 2));
        tm1 = fmaxf(tm1, __shfl_xor_sync(0xffffffffu, tm1, 1));
        tm1 = fmaxf(tm1, __shfl_xor_sync(0xffffffffu, tm1, 2));
        float mn0 = fmaxf(om0, tm0), mn1 = fmaxf(om1, tm1);
        float c0 = exp2f_fast((om0 - mn0) * L2E);
        float c1 = exp2f_fast((om1 - mn1) * L2E);
        om0 = mn0; om1 = mn1;
        const float nm0 = -mn0 * L2E, nm1 = -mn1 * L2E;

        float rs0 = 0.f, rs1 = 0.f;
        uint32_t pH01[8], pH23[8], pL01[8], pL23[8];
#pragma unroll
        for (int nb = 0; nb < 8; nb++) {
            float p0 = exp2f_fast(fmaf(s[nb][0], L2E, nm0));
            float p1 = exp2f_fast(fmaf(s[nb][1], L2E, nm0));
            float p2 = exp2f_fast(fmaf(s[nb][2], L2E, nm1));
            float p3 = exp2f_fast(fmaf(s[nb][3], L2E, nm1));
            rs0 += p0 + p1; rs1 += p2 + p3;
            __half h0 = __float2half_rn(p0), h1 = __float2half_rn(p1);
            __half h2 = __float2half_rn(p2), h3 = __float2half_rn(p3);
            __half l0 = __float2half_rn(p0 - __half2float(h0));
            __half l1 = __float2half_rn(p1 - __half2float(h1));
            __half l2 = __float2half_rn(p2 - __half2float(h2));
            __half l3 = __float2half_rn(p3 - __half2float(h3));
            __half a01[2] = {h0, h1}, a23[2] = {h2, h3};
            __half b01[2] = {l0, l1}, b23[2] = {l2, l3};
            pH01[nb] = *(uint32_t*)a01; pH23[nb] = *(uint32_t*)a23;
            pL01[nb] = *(uint32_t*)b01; pL23[nb] = *(uint32_t*)b23;
        }
        ol0 = fmaf(ol0, c0, rs0);
        ol1 = fmaf(ol1, c1, rs1);
#pragma unroll
        for (int db = 0; db < 8; db++) {
            o[db][0] *= c0; o[db][1] *= c0; o[db][2] *= c1; o[db][3] *= c1;
        }

        // ---- O += (Ph + Pl) * Vh  (V via ldmatrix.trans) ----
        const int tq = lane >> 3;
        const int krow_base = (tq & 1) * 8 + (lane & 7);
        const int ncol_base = (tq >> 1) * 8;
#pragma unroll
        for (int kc = 0; kc < 4; kc++) {
            const uint32_t ah0 = pH01[2*kc], ah1 = pH23[2*kc];
            const uint32_t ah2 = pH01[2*kc+1], ah3 = pH23[2*kc+1];
            const uint32_t al0 = pL01[2*kc], al1 = pL23[2*kc];
            const uint32_t al2 = pL01[2*kc+1], al3 = pL23[2*kc+1];
            const int krow = kc * 16 + krow_base;
            const uint32_t roff = (uint32_t)(krow * 128);
            const uint32_t rmsk = (uint32_t)((krow & 7) << 4);
#pragma unroll
            for (int dg = 0; dg < 4; dg++) {
                const uint32_t aoff = roff + (((uint32_t)((dg * 16 + ncol_base) * 2)) ^ rmsk);
                uint32_t v0, v1, v2, v3;
                ldmx4t(v0, v1, v2, v3, stb + 8192 + aoff);          // vhi
                mma16816h(o[2*dg],   ah0, ah1, ah2, ah3, v0, v1);
                mma16816h(o[2*dg+1], ah0, ah1, ah2, ah3, v2, v3);
                mma16816h(o[2*dg],   al0, al1, al2, al3, v0, v1);
                mma16816h(o[2*dg+1], al0, al1, al2, al3, v2, v3);
            }
        }
        __syncthreads();
    }

    // ---- row sum lives across the lane quad -> reduce before normalizing ----
    ol0 += __shfl_xor_sync(0xffffffffu, ol0, 1);
    ol0 += __shfl_xor_sync(0xffffffffu, ol0, 2);
    ol1 += __shfl_xor_sync(0xffffffffu, ol1, 1);
    ol1 += __shfl_xor_sync(0xffffffffu, ol1, 2);

    // ---- epilogue: normalize, split to fp16 hi/lo, store [B,N,C] ----
    const float i0 = 1.f / ol0, i1 = 1.f / ol1;
    const int r0 = m0 + warp * 16 + (lane >> 2), r1 = r0 + 8;
    const int cb = h * HDIM + (lane & 3) * 2;
#pragma unroll
    for (int db = 0; db < 8; db++) {
        const int c = cb + db * 8;
        float a0 = o[db][0] * i0, a1 = o[db][1] * i0;
        float a2 = o[db][2] * i1, a3 = o[db][3] * i1;
        __half h0 = __float2half_rn(a0), h1 = __float2half_rn(a1);
        __half h2 = __float2half_rn(a2), h3 = __float2half_rn(a3);
        __half l0 = __float2half_rn(a0 - __half2float(h0));
        __half l1 = __float2half_rn(a1 - __half2float(h1));
        __half l2 = __float2half_rn(a2 - __half2float(h2));
        __half l3 = __float2half_rn(a3 - __half2float(h3));
        __half hp01[2] = {h0, h1}, hp23[2] = {h2, h3};
        __half lp01[2] = {l0, l1}, lp23[2] = {l2, l3};
        *(uint32_t*)(OHi + (size_t)(b * NSEQ + r0) * DIMC + c) = *(uint32_t*)hp01;
        *(uint32_t*)(OLo + (size_t)(b * NSEQ + r0) * DIMC + c) = *(uint32_t*)lp01;
        *(uint32_t*)(OHi + (size_t)(b * NSEQ + r1) * DIMC + c) = *(uint32_t*)hp23;
        *(uint32_t*)(OLo + (size_t)(b * NSEQ + r1) * DIMC + c) = *(uint32_t*)lp23;
    }
}

// ============================================================
extern "C" void kernel_launch(void* const* d_in, const int* in_sizes, int n_in,
                              void* d_out, int out_size)
{
    const float* x      = (const float*)d_in[0];
    const float* pos    = (const float*)d_in[1];
    const float* qkv_w  = (const float*)d_in[2];
    const float* qnw    = (const float*)d_in[3];
    const float* knw    = (const float*)d_in[4];
    const float* proj_w = (const float*)d_in[5];
    const float* proj_b = (const float*)d_in[6];
    float* out = (float*)d_out;

    float *qkv;
    __half *xhi, *xlo, *whi, *phi, *ahi, *alo;
    __half *qhi, *qlo, *khi, *vhi;
    cudaGetSymbolAddress((void**)&qkv, g_qkv);
    cudaGetSymbolAddress((void**)&xhi, g_xhi);  cudaGetSymbolAddress((void**)&xlo, g_xlo);
    cudaGetSymbolAddress((void**)&whi, g_whi);
    cudaGetSymbolAddress((void**)&phi, g_phi);
    cudaGetSymbolAddress((void**)&ahi, g_ahi);  cudaGetSymbolAddress((void**)&alo, g_alo);
    cudaGetSymbolAddress((void**)&qhi, g_qhi);  cudaGetSymbolAddress((void**)&qlo, g_qlo);
    cudaGetSymbolAddress((void**)&khi, g_khi);  cudaGetSymbolAddress((void**)&vhi, g_vhi);

    cudaFuncSetAttribute(mma_gemm2<0>, cudaFuncAttributeMaxDynamicSharedMemorySize, SMEM_G2);
    cudaFuncSetAttribute(mma_gemm2<1>, cudaFuncAttributeMaxDynamicSharedMemorySize, SMEM_G2);
    cudaFuncSetAttribute(attn_mma, cudaFuncAttributeMaxDynamicSharedMemorySize, ATTN_SMEM);

    // 0) fp16 splits/rounds of inputs
    split_h2<<<(ROWS * DIMC / 4 + 255) / 256, 256>>>(x, xhi, xlo, ROWS * DIMC / 4);
    conv_h<<<(QKV_F * DIMC / 4 + 255) / 256, 256>>>(qkv_w, whi, QKV_F * DIMC / 4);
    conv_h<<<(DIMC * DIMC / 4 + 255) / 256, 256>>>(proj_w, phi, DIMC * DIMC / 4);

    // 1) QKV projection (fp16 2-term tensor cores)
    mma_gemm2<0><<<dim3(QKV_F / 128, ROWS / 128), 256, SMEM_G2>>>(
        xhi, xlo, whi, qkv, nullptr, QKV_F);

    // 2) RMSNorm + rotary: q 2-term, k/v single -> fp16 [B,H,N,D]
    rms_rot_kernel<<<(3 * BQ * NHEAD * NSEQ) / 8, 256>>>(
        qkv, pos, qnw, knw, qhi, qlo, khi, vhi);

    // 3) fp16 2-term tensor-core flash attention -> fp16 hi/lo [B,N,C]
    attn_mma<<<dim3(NSEQ / 128, NHEAD, BQ), 256, ATTN_SMEM>>>(
        qhi, qlo, khi, vhi, ahi, alo);

    // 4) proj (fp16 2-term tensor cores) + bias
    mma_gemm2<1><<<dim3(DIMC / 128, ROWS / 128), 256, SMEM_G2>>>(
        ahi, alo, phi, out, proj_b, DIMC);
}

// round 16
// speedup vs baseline: 5.9559x; 1.0200x over previous
#include <cuda_runtime.h>
#include <cuda_fp16.h>
#include <math.h>
#include <stdint.h>

#define DIMC  1024
#define NHEAD 16
#define HDIM  64
#define BQ    2
#define NSEQ  2048
#define ROWS  (BQ*NSEQ)      // 4096
#define QKV_F (3*DIMC)       // 3072
#define L2E   1.4426950408889634f

// ---- scratch (no allocations allowed) ----
__device__ __half g_xhi[ROWS * DIMC];
__device__ __half g_xlo[ROWS * DIMC];
__device__ __half g_whi[QKV_F * DIMC];
__device__ __half g_phi[DIMC * DIMC];
__device__ __half g_ahi[ROWS * DIMC];
__device__ __half g_alo[ROWS * DIMC];
// [B,H,N,D] fp16 operands for attention: Q 2-term, K/V single-rounded
__device__ __half g_qhi[ROWS * DIMC];
__device__ __half g_qlo[ROWS * DIMC];
__device__ __half g_khi[ROWS * DIMC];
__device__ __half g_vhi[ROWS * DIMC];

__device__ __forceinline__ uint32_t cvta_smem(const void* p) {
    uint32_t a;
    asm("{ .reg .u64 t; cvta.to.shared.u64 t, %1; cvt.u32.u64 %0, t; }" : "=r"(a) : "l"(p));
    return a;
}
__device__ __forceinline__ void cp16(uint32_t dst, const void* src) {
    asm volatile("cp.async.ca.shared.global [%0], [%1], 16;" :: "r"(dst), "l"(src));
}
__device__ __forceinline__ void cp_commit() {
    asm volatile("cp.async.commit_group;");
}
__device__ __forceinline__ void ldmx4(uint32_t& r0, uint32_t& r1, uint32_t& r2, uint32_t& r3,
                                      uint32_t addr) {
    asm volatile("ldmatrix.sync.aligned.m8n8.x4.shared.b16 {%0,%1,%2,%3}, [%4];"
                 : "=r"(r0), "=r"(r1), "=r"(r2), "=r"(r3) : "r"(addr));
}
__device__ __forceinline__ void ldmx4t(uint32_t& r0, uint32_t& r1, uint32_t& r2, uint32_t& r3,
                                       uint32_t addr) {
    asm volatile("ldmatrix.sync.aligned.m8n8.x4.trans.shared.b16 {%0,%1,%2,%3}, [%4];"
                 : "=r"(r0), "=r"(r1), "=r"(r2), "=r"(r3) : "r"(addr));
}
__device__ __forceinline__ void mma16816h(float* d,
                                          uint32_t a0, uint32_t a1, uint32_t a2, uint32_t a3,
                                          uint32_t b0, uint32_t b1) {
    asm volatile(
        "mma.sync.aligned.m16n8k16.row.col.f32.f16.f16.f32 "
        "{%0,%1,%2,%3}, {%4,%5,%6,%7}, {%8,%9}, {%0,%1,%2,%3};"
        : "+f"(d[0]), "+f"(d[1]), "+f"(d[2]), "+f"(d[3])
        : "r"(a0), "r"(a1), "r"(a2), "r"(a3), "r"(b0), "r"(b1));
}
__device__ __forceinline__ float exp2f_fast(float y) {
    y = fmaxf(y, -120.f);
    float t  = y + 12582912.f;
    float fl = t - 12582912.f;
    float fr = y - fl;
    float p = 0.0013333558f;
    p = fmaf(p, fr, 0.0096181291f);
    p = fmaf(p, fr, 0.0555041087f);
    p = fmaf(p, fr, 0.2402265069f);
    p = fmaf(p, fr, 0.6931471806f);
    p = fmaf(p, fr, 1.0f);
    int e = __float_as_int(t) << 23;
    return __int_as_float(__float_as_int(p) + e);
}

// ============================================================
// fp16 2-term GEMM (NT): C = (Ah + Al) * Bh^T
// FUSE=0: plain fp32 C + bias epilogue (proj).
// FUSE=1: fused rmsnorm+rope+fp16-split epilogue (QKV); the 128-col
//         tile holds exactly 2 heads, so the norm is CTA-local.
// ============================================================
#define KSEG 1024
#define NKT  16
#define OPND 16384
#define STAGE3 (3*OPND)
#define SMEM_G2 (2*STAGE3)      // 96KB; epilogue reuses 67.6KB of it
#define SROWF 132               // padded fp32 row stride for staging

template<int FUSE>
__global__ __launch_bounds__(256, 2) void mma_gemm2(
    const __half* __restrict__ Ah, const __half* __restrict__ Al,
    const __half* __restrict__ Bh,
    float* __restrict__ C, const float* __restrict__ bias, int ldC,
    const float* __restrict__ pos,
    const float* __restrict__ qnw, const float* __restrict__ knw,
    __half* __restrict__ qhi, __half* __restrict__ qlo,
    __half* __restrict__ khi, __half* __restrict__ vhi)
{
    extern __shared__ char smem[];
    const uint32_t sbase = cvta_smem(smem);

    const int tid  = threadIdx.x;
    const int warp = tid >> 5;
    const int lane = tid & 31;
    const int wm   = warp >> 2;
    const int wn   = warp & 3;
    const int m0 = blockIdx.y * 128;
    const int n0 = blockIdx.x * 128;

    const int lrow = tid >> 3;
    const int lch  = tid & 7;

    auto issue_tile = [&](int kt, int stg) {
        const int kc = kt * 64;
        const uint32_t base = sbase + stg * STAGE3;
#pragma unroll
        for (int i = 0; i < 4; i++) {
            int row = lrow + 32 * i;
            uint32_t soff = (uint32_t)(row * 128 + ((lch * 16) ^ ((row & 7) << 4)));
            cp16(base + soff,            Ah + (size_t)(m0 + row) * KSEG + kc + lch * 8);
            cp16(base + OPND + soff,     Al + (size_t)(m0 + row) * KSEG + kc + lch * 8);
            cp16(base + 2 * OPND + soff, Bh + (size_t)(n0 + row) * KSEG + kc + lch * 8);
        }
        cp_commit();
    };

    float acc[4][4][4];
#pragma unroll
    for (int i = 0; i < 4; i++)
#pragma unroll
        for (int j = 0; j < 4; j++)
#pragma unroll
            for (int v = 0; v < 4; v++) acc[i][j][v] = 0.f;

    const int lrow16 = lane & 15;
    const int lchunk = lane >> 4;
    uint32_t aRow[4], aMask[4];
#pragma unroll
    for (int fi = 0; fi < 4; fi++) {
        int r = wm * 64 + fi * 16 + lrow16;
        aRow[fi]  = (uint32_t)(r * 128);
        aMask[fi] = (uint32_t)((r & 7) << 4);
    }
    uint32_t bRow[2], bMask[2];
#pragma unroll
    for (int nj = 0; nj < 2; nj++) {
        int r = wn * 32 + nj * 16 + lrow16;
        bRow[nj]  = (uint32_t)(r * 128 + 2 * OPND);
        bMask[nj] = (uint32_t)((r & 7) << 4);
    }

    issue_tile(0, 0);
    issue_tile(1, 1);

    for (int kt = 0; kt < NKT; kt++) {
        if (kt + 1 < NKT) asm volatile("cp.async.wait_group 1;");
        else              asm volatile("cp.async.wait_group 0;");
        __syncthreads();

        const uint32_t base = sbase + (kt & 1) * STAGE3;
#pragma unroll
        for (int ks = 0; ks < 4; ks++) {
            const uint32_t kb = (uint32_t)(ks * 32 + lchunk * 16);
            uint32_t ah[4][4], al[4][4], b[2][4];
#pragma unroll
            for (int fi = 0; fi < 4; fi++) {
                ldmx4(ah[fi][0], ah[fi][1], ah[fi][2], ah[fi][3],
                      base + aRow[fi] + (kb ^ aMask[fi]));
                ldmx4(al[fi][0], al[fi][1], al[fi][2], al[fi][3],
                      base + OPND + aRow[fi] + (kb ^ aMask[fi]));
            }
#pragma unroll
            for (int nj = 0; nj < 2; nj++)
                ldmx4(b[nj][0], b[nj][1], b[nj][2], b[nj][3],
                      base + bRow[nj] + (kb ^ bMask[nj]));
#pragma unroll
            for (int fi = 0; fi < 4; fi++) {
#pragma unroll
                for (int nj = 0; nj < 2; nj++) {
                    mma16816h(acc[fi][2*nj],   ah[fi][0], ah[fi][1], ah[fi][2], ah[fi][3],
                              b[nj][0], b[nj][2]);
                    mma16816h(acc[fi][2*nj+1], ah[fi][0], ah[fi][1], ah[fi][2], ah[fi][3],
                              b[nj][1], b[nj][3]);
                    mma16816h(acc[fi][2*nj],   al[fi][0], al[fi][1], al[fi][2], al[fi][3],
                              b[nj][0], b[nj][2]);
                    mma16816h(acc[fi][2*nj+1], al[fi][0], al[fi][1], al[fi][2], al[fi][3],
                              b[nj][1], b[nj][3]);
                }
            }
        }
        __syncthreads();
        if (kt + 2 < NKT) issue_tile(kt + 2, kt & 1);
    }

    if constexpr (FUSE == 0) {
        // ---- plain epilogue: fp32 C + bias ----
        const int mrow = m0 + wm * 64 + (lane >> 2);
        const int ncol = n0 + wn * 32 + (lane & 3) * 2;
#pragma unroll
        for (int fi = 0; fi < 4; fi++) {
#pragma unroll
            for (int nb = 0; nb < 4; nb++) {
                int r = mrow + fi * 16;
                int c = ncol + nb * 8;
                float b0 = bias[c], b1 = bias[c + 1];
                *(float2*)&C[(size_t)r * ldC + c] =
                    make_float2(acc[fi][nb][0] + b0, acc[fi][nb][1] + b1);
                *(float2*)&C[(size_t)(r + 8) * ldC + c] =
                    make_float2(acc[fi][nb][2] + b0, acc[fi][nb][3] + b1);
            }
        }
    } else {
        // ---- fused epilogue: stage tile, rmsnorm+rope+split, write fp16 ----
        float* sC = (float*)smem;
        __syncthreads();   // all warps done with pipeline smem
        {
            const int r0 = wm * 64 + (lane >> 2);
            const int c0 = wn * 32 + (lane & 3) * 2;
#pragma unroll
            for (int fi = 0; fi < 4; fi++) {
#pragma unroll
                for (int nb = 0; nb < 4; nb++) {
                    int rr = r0 + fi * 16;
                    int cc = c0 + nb * 8;
                    sC[rr * SROWF + cc]           = acc[fi][nb][0];
                    sC[rr * SROWF + cc + 1]       = acc[fi][nb][1];
                    sC[(rr + 8) * SROWF + cc]     = acc[fi][nb][2];
                    sC[(rr + 8) * SROWF + cc + 1] = acc[fi][nb][3];
                }
            }
        }
        __syncthreads();

        const int row  = tid >> 1;          // 0..127 token within tile
        const int hh   = tid & 1;           // head within tile
        const int gtok = m0 + row;
        const int bb   = gtok >> 11;        // batch
        const int tok  = gtok & (NSEQ - 1);
        const int region = n0 >> 10;        // 0=q, 1=k, 2=v
        const int hglob  = ((n0 & 1023) >> 6) + hh;
        const float* srcrow = sC + row * SROWF + hh * 64;
        const size_t dofs = ((size_t)(bb * NHEAD + hglob) * NSEQ + tok) * HDIM;

        if (region == 2) {
            // v: plain fp16 round
#pragma unroll
            for (int c = 0; c < 8; c++) {
                float4 v0 = *(const float4*)(srcrow + c * 8);
                float4 v1 = *(const float4*)(srcrow + c * 8 + 4);
                __half hp[8] = {
                    __float2half_rn(v0.x), __float2half_rn(v0.y),
                    __float2half_rn(v0.z), __float2half_rn(v0.w),
                    __float2half_rn(v1.x), __float2half_rn(v1.y),
                    __float2half_rn(v1.z), __float2half_rn(v1.w)};
                *(uint4*)(vhi + dofs + c * 8) = *(const uint4*)hp;
            }
        } else {
            float ss = 0.f;
#pragma unroll
            for (int c = 0; c < 16; c++) {
                float4 v = *(const float4*)(srcrow + c * 4);
                ss += v.x * v.x + v.y * v.y + v.z * v.z + v.w * v.w;
            }
            const float rr = rsqrtf(ss * (1.f / HDIM) + 1e-6f);
            const float* w = region ? knw : qnw;
            const float qs = region ? 1.f : 0.125f;
#pragma unroll
            for (int c = 0; c < 8; c++) {
                float4 v0 = *(const float4*)(srcrow + c * 8);
                float4 v1 = *(const float4*)(srcrow + c * 8 + 4);
                float xv[8] = {v0.x, v0.y, v0.z, v0.w, v1.x, v1.y, v1.z, v1.w};
                __half hp[8], lp[8];
#pragma unroll
                for (int p = 0; p < 4; p++) {
                    float xr = xv[2*p]     * rr * w[c * 8 + 2*p];
                    float xi = xv[2*p + 1] * rr * w[c * 8 + 2*p + 1];
                    float ang = pos[tok * (HDIM / 2) + c * 4 + p];
                    float sn, cs;
                    __sincosf(ang, &sn, &cs);
                    float o0 = (xr * cs - xi * sn) * qs;
                    float o1 = (xr * sn + xi * cs) * qs;
                    hp[2*p]     = __float2half_rn(o0);
                    hp[2*p + 1] = __float2half_rn(o1);
                    if (region == 0) {
                        lp[2*p]     = __float2half_rn(o0 - __half2float(hp[2*p]));
                        lp[2*p + 1] = __float2half_rn(o1 - __half2float(hp[2*p + 1]));
                    }
                }
                if (region == 0) {
                    *(uint4*)(qhi + dofs + c * 8) = *(const uint4*)hp;
                    *(uint4*)(qlo + dofs + c * 8) = *(const uint4*)lp;
                } else {
                    *(uint4*)(khi + dofs + c * 8) = *(const uint4*)hp;
                }
            }
        }
    }
}

// ============================================================
// fp32 -> fp16 exact 2-term split
// ============================================================
__global__ __launch_bounds__(256) void split_h2(
    const float* __restrict__ in, __half* __restrict__ hi,
    __half* __restrict__ lo, int n4)
{
    int i = blockIdx.x * blockDim.x + threadIdx.x;
    if (i >= n4) return;
    float4 v = ((const float4*)in)[i];
    __half h[4], l[4];
    float x[4] = {v.x, v.y, v.z, v.w};
#pragma unroll
    for (int j = 0; j < 4; j++) {
        h[j] = __float2half_rn(x[j]);
        l[j] = __float2half_rn(x[j] - __half2float(h[j]));
    }
    ((uint2*)hi)[i] = *(const uint2*)h;
    ((uint2*)lo)[i] = *(const uint2*)l;
}

// fp32 -> fp16 single round
__global__ __launch_bounds__(256) void conv_h(
    const float* __restrict__ in, __half* __restrict__ hi, int n4)
{
    int i = blockIdx.x * blockDim.x + threadIdx.x;
    if (i >= n4) return;
    float4 v = ((const float4*)in)[i];
    __half h[4] = {__float2half_rn(v.x), __float2half_rn(v.y),
                   __float2half_rn(v.z), __float2half_rn(v.w)};
    ((uint2*)hi)[i] = *(const uint2*)h;
}

// ============================================================
// Tensor-core flash attention, fp16 2-term (unchanged from R12).
// ============================================================
#define ATTN_STAGE 16384
#define ATTN_SMEM  (2*ATTN_STAGE)

__global__ __launch_bounds__(256) void attn_mma(
    const __half* __restrict__ Qh, const __half* __restrict__ Ql,
    const __half* __restrict__ Kh, const __half* __restrict__ Vh,
    __half* __restrict__ OHi, __half* __restrict__ OLo)
{
    extern __shared__ __align__(16) char sm[];
    const uint32_t sb = cvta_smem(sm);

    const int tid = threadIdx.x, warp = tid >> 5, lane = tid & 31;
    const int m0 = blockIdx.x * 128;
    const int h = blockIdx.y, b = blockIdx.z;
    const size_t hoff = (size_t)((b * NHEAD + h) * NSEQ);

    const int lrow16 = lane & 15, lchunk = lane >> 4;

    uint32_t qfh[4][4], qfl[4][4];
    {
        const __half* Qsrc[2] = {Qh, Ql};
        const int r = warp * 16 + lrow16;
        const uint32_t rb = (uint32_t)(r * 128), msk = (uint32_t)((r & 7) << 4);
        for (int pass = 0; pass < 2; pass++) {
#pragma unroll
            for (int i = 0; i < 4; i++) {
                int id = tid + 256 * i;
                int row = id >> 3, ch = id & 7;
                *(uint4*)(sm + row * 128 + ((ch * 16) ^ ((row & 7) << 4))) =
                    *(const uint4*)(Qsrc[pass] + (hoff + m0 + row) * HDIM + ch * 8);
            }
            __syncthreads();
#pragma unroll
            for (int kc = 0; kc < 4; kc++) {
                uint32_t addr = sb + rb + (((uint32_t)(kc * 32 + lchunk * 16)) ^ msk);
                if (pass == 0) ldmx4(qfh[kc][0], qfh[kc][1], qfh[kc][2], qfh[kc][3], addr);
                else           ldmx4(qfl[kc][0], qfl[kc][1], qfl[kc][2], qfl[kc][3], addr);
            }
            __syncthreads();
        }
    }

    float o[8][4];
#pragma unroll
    for (int i = 0; i < 8; i++)
#pragma unroll
        for (int j = 0; j < 4; j++) o[i][j] = 0.f;
    float om0 = -1e30f, om1 = -1e30f, ol0 = 0.f, ol1 = 0.f;

    const __half* srcs[2] = {Kh, Vh};

    auto issue_kv = [&](int j0, int stg) {
#pragma unroll
        for (int i = 0; i < 4; i++) {
            int id = tid + 256 * i;
            int arr = id >> 9, row = (id >> 3) & 63, ch = id & 7;
            cp16(sb + stg * ATTN_STAGE + arr * 8192 +
                     (uint32_t)(row * 128 + ((ch * 16) ^ ((row & 7) << 4))),
                 srcs[arr] + (hoff + j0 + row) * HDIM + ch * 8);
        }
        cp_commit();
    };

    issue_kv(0, 0);

    const int NT = NSEQ / 64;
    for (int t = 0; t < NT; t++) {
        const int buf = t & 1;
        if (t + 1 < NT) {
            issue_kv((t + 1) * 64, buf ^ 1);
            asm volatile("cp.async.wait_group 1;");
        } else {
            asm volatile("cp.async.wait_group 0;");
        }
        __syncthreads();
        const uint32_t stb = sb + buf * ATTN_STAGE;

        float s[8][4];
#pragma unroll
        for (int i = 0; i < 8; i++)
#pragma unroll
            for (int j = 0; j < 4; j++) s[i][j] = 0.f;
#pragma unroll
        for (int ng = 0; ng < 4; ng++) {
            const int r = ng * 16 + lrow16;
            const uint32_t rb = (uint32_t)(r * 128), msk = (uint32_t)((r & 7) << 4);
#pragma unroll
            for (int kc = 0; kc < 4; kc++) {
                const uint32_t co = (((uint32_t)(kc * 32 + lchunk * 16)) ^ msk);
                uint32_t k0, k1, k2, k3;
                ldmx4(k0, k1, k2, k3, stb + rb + co);
                mma16816h(s[2*ng],   qfh[kc][0], qfh[kc][1], qfh[kc][2], qfh[kc][3], k0, k2);
                mma16816h(s[2*ng+1], qfh[kc][0], qfh[kc][1], qfh[kc][2], qfh[kc][3], k1, k3);
                mma16816h(s[2*ng],   qfl[kc][0], qfl[kc][1], qfl[kc][2], qfl[kc][3], k0, k2);
                mma16816h(s[2*ng+1], qfl[kc][0], qfl[kc][1], qfl[kc][2], qfl[kc][3], k1, k3);
            }
        }

        float tm0 = -1e30f, tm1 = -1e30f;
#pragma unroll
        for (int nb = 0; nb < 8; nb++) {
            tm0 = fmaxf(tm0, fmaxf(s[nb][0], s[nb][1]));
            tm1 = fmaxf(tm1, fmaxf(s[nb][2], s[nb][3]));
        }
        tm0 = fmaxf(tm0, __shfl_xor_sync(0xffffffffu, tm0, 1));
        tm0 = fmaxf(tm0, __shfl_xor_sync(0xffffffffu, tm0, 2));
        tm1 = fmaxf(tm1, __shfl_xor_sync(0xffffffffu, tm1, 1));
        tm1 = fmaxf(tm1, __shfl_xor_sync(0xffffffffu, tm1, 2));
        float mn0 = fmaxf(om0, tm0), mn1 = fmaxf(om1, tm1);
        float c0 = exp2f_fast((om0 - mn0) * L2E);
        float c1 = exp2f_fast((om1 - mn1) * L2E);
        om0 = mn0; om1 = mn1;
        const float nm0 = -mn0 * L2E, nm1 = -mn1 * L2E;

        float rs0 = 0.f, rs1 = 0.f;
        uint32_t pH01[8], pH23[8], pL01[8], pL23[8];
#pragma unroll
        for (int nb = 0; nb < 8; nb++) {
            float p0 = exp2f_fast(fmaf(s[nb][0], L2E, nm0));
            float p1 = exp2f_fast(fmaf(s[nb][1], L2E, nm0));
            float p2 = exp2f_fast(fmaf(s[nb][2], L2E, nm1));
            float p3 = exp2f_fast(fmaf(s[nb][3], L2E, nm1));
            rs0 += p0 + p1; rs1 += p2 + p3;
            __half h0 = __float2half_rn(p0), h1 = __float2half_rn(p1);
            __half h2 = __float2half_rn(p2), h3 = __float2half_rn(p3);
            __half l0 = __float2half_rn(p0 - __half2float(h0));
            __half l1 = __float2half_rn(p1 - __half2float(h1));
            __half l2 = __float2half_rn(p2 - __half2float(h2));
            __half l3 = __float2half_rn(p3 - __half2float(h3));
            __half a01[2] = {h0, h1}, a23[2] = {h2, h3};
            __half b01[2] = {l0, l1}, b23[2] = {l2, l3};
            pH01[nb] = *(uint32_t*)a01; pH23[nb] = *(uint32_t*)a23;
            pL01[nb] = *(uint32_t*)b01; pL23[nb] = *(uint32_t*)b23;
        }
        ol0 = fmaf(ol0, c0, rs0);
        ol1 = fmaf(ol1, c1, rs1);
#pragma unroll
        for (int db = 0; db < 8; db++) {
            o[db][0] *= c0; o[db][1] *= c0; o[db][2] *= c1; o[db][3] *= c1;
        }

        const int tq = lane >> 3;
        const int krow_base = (tq & 1) * 8 + (lane & 7);
        const int ncol_base = (tq >> 1) * 8;
#pragma unroll
        for (int kc = 0; kc < 4; kc++) {
            const uint32_t ah0 = pH01[2*kc], ah1 = pH23[2*kc];
            const uint32_t ah2 = pH01[2*kc+1], ah3 = pH23[2*kc+1];
            const uint32_t al0 = pL01[2*kc], al1 = pL23[2*kc];
            const uint32_t al2 = pL01[2*kc+1], al3 = pL23[2*kc+1];
            const int krow = kc * 16 + krow_base;
            const uint32_t roff = (uint32_t)(krow * 128);
            const uint32_t rmsk = (uint32_t)((krow & 7) << 4);
#pragma unroll
            for (int dg = 0; dg < 4; dg++) {
                const uint32_t aoff = roff + (((uint32_t)((dg * 16 + ncol_base) * 2)) ^ rmsk);
                uint32_t v0, v1, v2, v3;
                ldmx4t(v0, v1, v2, v3, stb + 8192 + aoff);
                mma16816h(o[2*dg],   ah0, ah1, ah2, ah3, v0, v1);
                mma16816h(o[2*dg+1], ah0, ah1, ah2, ah3, v2, v3);
                mma16816h(o[2*dg],   al0, al1, al2, al3, v0, v1);
                mma16816h(o[2*dg+1], al0, al1, al2, al3, v2, v3);
            }
        }
        __syncthreads();
    }

    ol0 += __shfl_xor_sync(0xffffffffu, ol0, 1);
    ol0 += __shfl_xor_sync(0xffffffffu, ol0, 2);
    ol1 += __shfl_xor_sync(0xffffffffu, ol1, 1);
    ol1 += __shfl_xor_sync(0xffffffffu, ol1, 2);

    const float i0 = 1.f / ol0, i1 = 1.f / ol1;
    const int r0 = m0 + warp * 16 + (lane >> 2), r1 = r0 + 8;
    const int cb = h * HDIM + (lane & 3) * 2;
#pragma unroll
    for (int db = 0; db < 8; db++) {
        const int c = cb + db * 8;
        float a0 = o[db][0] * i0, a1 = o[db][1] * i0;
        float a2 = o[db][2] * i1, a3 = o[db][3] * i1;
        __half h0 = __float2half_rn(a0), h1 = __float2half_rn(a1);
        __half h2 = __float2half_rn(a2), h3 = __float2half_rn(a3);
        __half l0 = __float2half_rn(a0 - __half2float(h0));
        __half l1 = __float2half_rn(a1 - __half2float(h1));
        __half l2 = __float2half_rn(a2 - __half2float(h2));
        __half l3 = __float2half_rn(a3 - __half2float(h3));
        __half hp01[2] = {h0, h1}, hp23[2] = {h2, h3};
        __half lp01[2] = {l0, l1}, lp23[2] = {l2, l3};
        *(uint32_t*)(OHi + (size_t)(b * NSEQ + r0) * DIMC + c) = *(uint32_t*)hp01;
        *(uint32_t*)(OLo + (size_t)(b * NSEQ + r0) * DIMC + c) = *(uint32_t*)lp01;
        *(uint32_t*)(OHi + (size_t)(b * NSEQ + r1) * DIMC + c) = *(uint32_t*)hp23;
        *(uint32_t*)(OLo + (size_t)(b * NSEQ + r1) * DIMC + c) = *(uint32_t*)lp23;
    }
}

// ============================================================
extern "C" void kernel_launch(void* const* d_in, const int* in_sizes, int n_in,
                              void* d_out, int out_size)
{
    const float* x      = (const float*)d_in[0];
    const float* pos    = (const float*)d_in[1];
    const float* qkv_w  = (const float*)d_in[2];
    const float* qnw    = (const float*)d_in[3];
    const float* knw    = (const float*)d_in[4];
    const float* proj_w = (const float*)d_in[5];
    const float* proj_b = (const float*)d_in[6];
    float* out = (float*)d_out;

    __half *xhi, *xlo, *whi, *phi, *ahi, *alo;
    __half *qhi, *qlo, *khi, *vhi;
    cudaGetSymbolAddress((void**)&xhi, g_xhi);  cudaGetSymbolAddress((void**)&xlo, g_xlo);
    cudaGetSymbolAddress((void**)&whi, g_whi);
    cudaGetSymbolAddress((void**)&phi, g_phi);
    cudaGetSymbolAddress((void**)&ahi, g_ahi);  cudaGetSymbolAddress((void**)&alo, g_alo);
    cudaGetSymbolAddress((void**)&qhi, g_qhi);  cudaGetSymbolAddress((void**)&qlo, g_qlo);
    cudaGetSymbolAddress((void**)&khi, g_khi);  cudaGetSymbolAddress((void**)&vhi, g_vhi);

    cudaFuncSetAttribute(mma_gemm2<0>, cudaFuncAttributeMaxDynamicSharedMemorySize, SMEM_G2);
    cudaFuncSetAttribute(mma_gemm2<1>, cudaFuncAttributeMaxDynamicSharedMemorySize, SMEM_G2);
    cudaFuncSetAttribute(attn_mma, cudaFuncAttributeMaxDynamicSharedMemorySize, ATTN_SMEM);

    // 0) fp16 splits/rounds of inputs
    split_h2<<<(ROWS * DIMC / 4 + 255) / 256, 256>>>(x, xhi, xlo, ROWS * DIMC / 4);
    conv_h<<<(QKV_F * DIMC / 4 + 255) / 256, 256>>>(qkv_w, whi, QKV_F * DIMC / 4);
    conv_h<<<(DIMC * DIMC / 4 + 255) / 256, 256>>>(proj_w, phi, DIMC * DIMC / 4);

    // 1) QKV projection with FUSED rmsnorm+rope+split epilogue
    mma_gemm2<1><<<dim3(QKV_F / 128, ROWS / 128), 256, SMEM_G2>>>(
        xhi, xlo, whi, nullptr, nullptr, 0,
        pos, qnw, knw, qhi, qlo, khi, vhi);

    // 2) fp16 2-term tensor-core flash attention -> fp16 hi/lo [B,N,C]
    attn_mma<<<dim3(NSEQ / 128, NHEAD, BQ), 256, ATTN_SMEM>>>(
        qhi, qlo, khi, vhi, ahi, alo);

    // 3) proj (fp16 2-term tensor cores) + bias
    mma_gemm2<0><<<dim3(DIMC / 128, ROWS / 128), 256, SMEM_G2>>>(
        ahi, alo, phi, out, proj_b, DIMC,
        nullptr, nullptr, nullptr, nullptr, nullptr, nullptr, nullptr);
}